// round 1
// baseline (speedup 1.0000x reference)
#include <cuda_runtime.h>

#define N_TOK   49
#define CDIM    128
#define NH      4
#define DH      32
#define QKV_N   384
#define NWIN    64
#define NTHREADS 384
#define SCALE   0.17677669529663687f   /* 32^-0.5 */

// smem layout (floats): xs[51*128] (reused as attention output), q[49*128], k[49*128], v[49*128]
#define XS_ROWS 51
#define SMEM_FLOATS (XS_ROWS*CDIM + 3*N_TOK*CDIM)

__global__ void __launch_bounds__(NTHREADS, 1)
win_attn_kernel(const float* __restrict__ x,
                const float* __restrict__ mask,
                const float* __restrict__ qkv_w,
                const float* __restrict__ qkv_b,
                const float* __restrict__ proj_w,
                const float* __restrict__ proj_b,
                const float* __restrict__ bias_table,
                const int*   __restrict__ rel_index,
                float* __restrict__ out)
{
    extern __shared__ float smem[];
    float* xs = smem;                       // 51*128, x then reused as attn output
    float* qs = smem + XS_ROWS*CDIM;        // 49*128 (pre-scaled q)
    float* ks = qs + N_TOK*CDIM;            // 49*128
    float* vs = ks + N_TOK*CDIM;            // 49*128

    const int b   = blockIdx.x;
    const int tid = threadIdx.x;

    // ---------------- Phase 1: load x window into smem ----------------
    {
        const float4* xb = (const float4*)(x + (size_t)b * (N_TOK*CDIM));
        for (int idx = tid; idx < (N_TOK*CDIM)/4; idx += NTHREADS)
            ((float4*)xs)[idx] = xb[idx];
    }
    __syncthreads();

    // ---------------- Phase 2: qkv = x @ qkv_w + qkv_b ----------------
    // thread tid computes column tid (of 384) for all 49 rows
    {
        const int j = tid;
        float acc[N_TOK];
        const float bj = qkv_b[j];
        #pragma unroll
        for (int i = 0; i < N_TOK; ++i) acc[i] = bj;

        for (int k = 0; k < CDIM; k += 4) {
            const float w0 = qkv_w[(k+0)*QKV_N + j];
            const float w1 = qkv_w[(k+1)*QKV_N + j];
            const float w2 = qkv_w[(k+2)*QKV_N + j];
            const float w3 = qkv_w[(k+3)*QKV_N + j];
            #pragma unroll
            for (int i = 0; i < N_TOK; ++i) {
                const float4 xv = *(const float4*)&xs[i*CDIM + k];
                acc[i] = fmaf(xv.x, w0, acc[i]);
                acc[i] = fmaf(xv.y, w1, acc[i]);
                acc[i] = fmaf(xv.z, w2, acc[i]);
                acc[i] = fmaf(xv.w, w3, acc[i]);
            }
        }

        float* dst; int col;
        if (j < CDIM) {
            dst = qs; col = j;
            #pragma unroll
            for (int i = 0; i < N_TOK; ++i) acc[i] *= SCALE;
        } else if (j < 2*CDIM) {
            dst = ks; col = j - CDIM;
        } else {
            dst = vs; col = j - 2*CDIM;
        }
        #pragma unroll
        for (int i = 0; i < N_TOK; ++i) dst[i*CDIM + col] = acc[i];
    }
    __syncthreads();

    // ---------------- Phase 3+4: attention (one thread per (head,row)) ----------------
    if (tid < NH * N_TOK) {
        const int h = tid / N_TOK;
        const int i = tid - h * N_TOK;

        float qr[DH];
        {
            const float* qrow = qs + i*CDIM + h*DH;
            #pragma unroll
            for (int d = 0; d < DH; d += 4) {
                const float4 t = *(const float4*)&qrow[d];
                qr[d]=t.x; qr[d+1]=t.y; qr[d+2]=t.z; qr[d+3]=t.w;
            }
        }
        const int w = b & (NWIN-1);
        const float* mrow = mask + ((size_t)w*N_TOK + i)*N_TOK;
        const int*   rrow = rel_index + i*N_TOK;

        float sc[N_TOK];
        #pragma unroll
        for (int m = 0; m < N_TOK; ++m) {
            const float* krow = ks + m*CDIM + h*DH;
            float s = 0.f;
            #pragma unroll
            for (int d = 0; d < DH; d += 4) {
                const float4 kv = *(const float4*)&krow[d];
                s = fmaf(qr[d+0], kv.x, s);
                s = fmaf(qr[d+1], kv.y, s);
                s = fmaf(qr[d+2], kv.z, s);
                s = fmaf(qr[d+3], kv.w, s);
            }
            s += bias_table[rrow[m]*NH + h];
            s += mrow[m];
            sc[m] = s;
        }

        // softmax over m
        float mx = sc[0];
        #pragma unroll
        for (int m = 1; m < N_TOK; ++m) mx = fmaxf(mx, sc[m]);
        float sum = 0.f;
        #pragma unroll
        for (int m = 0; m < N_TOK; ++m) {
            const float e = __expf(sc[m] - mx);
            sc[m] = e;
            sum += e;
        }
        const float inv = 1.f / sum;

        // PV
        float acc[DH];
        #pragma unroll
        for (int d = 0; d < DH; ++d) acc[d] = 0.f;
        #pragma unroll
        for (int m = 0; m < N_TOK; ++m) {
            const float pm = sc[m];
            const float* vrow = vs + m*CDIM + h*DH;
            #pragma unroll
            for (int d = 0; d < DH; d += 4) {
                const float4 vv = *(const float4*)&vrow[d];
                acc[d+0] = fmaf(pm, vv.x, acc[d+0]);
                acc[d+1] = fmaf(pm, vv.y, acc[d+1]);
                acc[d+2] = fmaf(pm, vv.z, acc[d+2]);
                acc[d+3] = fmaf(pm, vv.w, acc[d+3]);
            }
        }
        // write attention output into xs (x is dead)
        float* orow = xs + i*CDIM + h*DH;
        #pragma unroll
        for (int d = 0; d < DH; ++d) orow[d] = acc[d] * inv;
    }
    // zero padding rows 49,50 of attn-output buffer (used by proj row-group tiling)
    if (tid < 2*CDIM) xs[N_TOK*CDIM + tid] = 0.f;
    __syncthreads();

    // ---------------- Phase 5: out = attn_out @ proj_w + proj_b ----------------
    {
        const int c  = tid & (CDIM-1);   // column 0..127
        const int rg = tid >> 7;         // row group 0..2, rows rg, rg+3, rg+6, ...
        float pacc[17];
        const float pb = proj_b[c];
        #pragma unroll
        for (int r = 0; r < 17; ++r) pacc[r] = pb;

        for (int k = 0; k < CDIM; k += 4) {
            const float w0 = proj_w[(k+0)*CDIM + c];
            const float w1 = proj_w[(k+1)*CDIM + c];
            const float w2 = proj_w[(k+2)*CDIM + c];
            const float w3 = proj_w[(k+3)*CDIM + c];
            #pragma unroll
            for (int r = 0; r < 17; ++r) {
                const int i = rg + 3*r;   // <= 50, padded rows are zero
                const float4 xv = *(const float4*)&xs[i*CDIM + k];
                pacc[r] = fmaf(xv.x, w0, pacc[r]);
                pacc[r] = fmaf(xv.y, w1, pacc[r]);
                pacc[r] = fmaf(xv.z, w2, pacc[r]);
                pacc[r] = fmaf(xv.w, w3, pacc[r]);
            }
        }
        float* ob = out + (size_t)b * (N_TOK*CDIM);
        #pragma unroll
        for (int r = 0; r < 17; ++r) {
            const int i = rg + 3*r;
            if (i < N_TOK) ob[i*CDIM + c] = pacc[r];
        }
    }
}

extern "C" void kernel_launch(void* const* d_in, const int* in_sizes, int n_in,
                              void* d_out, int out_size)
{
    const float* x          = (const float*)d_in[0];
    const float* mask       = (const float*)d_in[1];
    const float* qkv_w      = (const float*)d_in[2];
    const float* qkv_b      = (const float*)d_in[3];
    const float* proj_w     = (const float*)d_in[4];
    const float* proj_b     = (const float*)d_in[5];
    const float* bias_table = (const float*)d_in[6];
    const int*   rel_index  = (const int*)d_in[7];
    float* out = (float*)d_out;

    const int B = in_sizes[0] / (N_TOK * CDIM);   // 4096 windows
    const size_t shmem = SMEM_FLOATS * sizeof(float);   // ~99 KB
    cudaFuncSetAttribute(win_attn_kernel,
                         cudaFuncAttributeMaxDynamicSharedMemorySize, (int)shmem);
    win_attn_kernel<<<B, NTHREADS, shmem>>>(x, mask, qkv_w, qkv_b,
                                            proj_w, proj_b, bias_table, rel_index, out);
}

// round 2
// speedup vs baseline: 1.0625x; 1.0625x over previous
#include <cuda_runtime.h>

#define N_TOK    49
#define CDIM     128
#define NH       4
#define DH       32
#define QKV_N    384
#define NWIN     64
#define NTHREADS 384
#define SCALE    0.17677669529663687f   /* 32^-0.5 */

// smem row pitches (floats)
#define PX   60   // xT / aoT pitch: rows 0..59 (proj reads pairs up to row 59)
#define PQ   58   // qT/kT/vT pitch: rows 0..55 written by qkv phase

// smem float offsets
#define OFF_XT  0
#define OFF_QT  (128*PX)                 // 7680
#define OFF_KT  (OFF_QT + 128*PQ)        // 15104
#define OFF_VT  (OFF_KT + 128*PQ)        // 22528
#define SMEM_FLOATS (OFF_VT + 128*PQ)    // 29952 floats = 119808 B

typedef unsigned long long u64;

__device__ __forceinline__ u64 pack2(float lo, float hi) {
    u64 r; asm("mov.b64 %0, {%1, %2};" : "=l"(r) : "f"(lo), "f"(hi)); return r;
}
__device__ __forceinline__ void unpack2(u64 v, float& lo, float& hi) {
    asm("mov.b64 {%0, %1}, %2;" : "=f"(lo), "=f"(hi) : "l"(v));
}
__device__ __forceinline__ u64 fma2(u64 a, u64 b, u64 c) {
    u64 d; asm("fma.rn.f32x2 %0, %1, %2, %3;" : "=l"(d) : "l"(a), "l"(b), "l"(c)); return d;
}
__device__ __forceinline__ u64 mul2(u64 a, u64 b) {
    u64 d; asm("mul.rn.f32x2 %0, %1, %2;" : "=l"(d) : "l"(a), "l"(b)); return d;
}

// fused rel-pos-bias + shift-window mask: abias[w][h][i][m]
__device__ float g_abias[NWIN * NH * N_TOK * N_TOK];

__global__ void build_abias_kernel(const float* __restrict__ mask,
                                   const float* __restrict__ bias_table,
                                   const int*   __restrict__ rel_index)
{
    int idx = blockIdx.x * blockDim.x + threadIdx.x;
    const int TOT = NWIN * NH * N_TOK * N_TOK;
    if (idx >= TOT) return;
    int m = idx % N_TOK;
    int i = (idx / N_TOK) % N_TOK;
    int h = (idx / (N_TOK * N_TOK)) % NH;
    int w = idx / (NH * N_TOK * N_TOK);
    float rpb = bias_table[rel_index[i * N_TOK + m] * NH + h];
    float mk  = mask[(w * N_TOK + i) * N_TOK + m];
    g_abias[idx] = rpb + mk;
}

__global__ void __launch_bounds__(NTHREADS, 1)
win_attn_kernel(const float* __restrict__ x,
                const float* __restrict__ qkv_w,
                const float* __restrict__ qkv_b,
                const float* __restrict__ proj_w,
                const float* __restrict__ proj_b,
                float* __restrict__ out)
{
    extern __shared__ float smem[];
    float* xT = smem + OFF_XT;   // [col k][row i], pitch PX; later reused as aoT
    float* qT = smem + OFF_QT;   // [col j][row i], pitch PQ (pre-scaled q)
    float* kT = smem + OFF_KT;
    float* vT = smem + OFF_VT;

    const int b   = blockIdx.x;
    const int tid = threadIdx.x;

    // ---------- Phase 1: load x (coalesced) -> transposed smem; zero pad rows ----------
    {
        const float4* xb = (const float4*)(x + (size_t)b * (N_TOK * CDIM));
        for (int idx = tid; idx < (N_TOK * CDIM) / 4; idx += NTHREADS) {
            float4 v = xb[idx];
            int i  = idx >> 5;           // 32 float4 per row
            int k4 = (idx & 31) * 4;
            xT[(k4 + 0) * PX + i] = v.x;
            xT[(k4 + 1) * PX + i] = v.y;
            xT[(k4 + 2) * PX + i] = v.z;
            xT[(k4 + 3) * PX + i] = v.w;
        }
        // zero rows 49..59 of xT (used as zero-pad by qkv GEMM and by proj via aoT)
        for (int idx = tid; idx < 128 * 11; idx += NTHREADS) {
            int k = idx & 127;
            int r = 49 + (idx >> 7);
            xT[k * PX + r] = 0.f;
        }
    }
    __syncthreads();

    // ---------- Phase 2: qkv = x @ qkv_w + b  (4 cols x 7 row-pairs per thread) ----------
    {
        const int cg = tid >> 2;          // 0..95 : columns 4*cg..4*cg+3
        const int rg = tid & 3;           // 0..3  : row-pairs rg*7..rg*7+6 (rows 2P,2P+1)
        const int j0 = cg * 4;
        const int rb = rg * 14;           // base row (even)

        u64 acc[4][7];
        #pragma unroll
        for (int c = 0; c < 4; ++c) {
            float bj = qkv_b[j0 + c];
            u64 bj2 = pack2(bj, bj);
            #pragma unroll
            for (int p = 0; p < 7; ++p) acc[c][p] = bj2;
        }

        #pragma unroll 2
        for (int k = 0; k < CDIM; ++k) {
            const float4 w4 = *(const float4*)&qkv_w[k * QKV_N + j0];
            u64 wb0 = pack2(w4.x, w4.x);
            u64 wb1 = pack2(w4.y, w4.y);
            u64 wb2 = pack2(w4.z, w4.z);
            u64 wb3 = pack2(w4.w, w4.w);
            const float* xr = &xT[k * PX + rb];
            u64 xp[7];
            #pragma unroll
            for (int p = 0; p < 7; ++p) xp[p] = *(const u64*)&xr[2 * p];
            #pragma unroll
            for (int p = 0; p < 7; ++p) {
                acc[0][p] = fma2(xp[p], wb0, acc[0][p]);
                acc[1][p] = fma2(xp[p], wb1, acc[1][p]);
                acc[2][p] = fma2(xp[p], wb2, acc[2][p]);
                acc[3][p] = fma2(xp[p], wb3, acc[3][p]);
            }
        }

        float* dst; int col;
        if (j0 < CDIM)           { dst = qT; col = j0; }
        else if (j0 < 2 * CDIM)  { dst = kT; col = j0 - CDIM; }
        else                     { dst = vT; col = j0 - 2 * CDIM; }

        if (j0 < CDIM) {
            const u64 s2 = pack2(SCALE, SCALE);
            #pragma unroll
            for (int c = 0; c < 4; ++c)
                #pragma unroll
                for (int p = 0; p < 7; ++p) acc[c][p] = mul2(acc[c][p], s2);
        }
        #pragma unroll
        for (int c = 0; c < 4; ++c)
            #pragma unroll
            for (int p = 0; p < 7; ++p)
                *(u64*)&dst[(col + c) * PQ + rb + 2 * p] = acc[c][p];
    }
    __syncthreads();

    // ---------- Phase 3+4: attention. thread = (head h, row i), 256 lanes ----------
    if (tid < 256) {
        const int h  = tid >> 6;          // warp-uniform
        const int i  = tid & 63;
        const int ii = (i < N_TOK) ? i : (N_TOK - 1);

        u64 sc2[25];
        #pragma unroll
        for (int mp = 0; mp < 25; ++mp) sc2[mp] = pack2(0.f, 0.f);

        // scores: d-outer, m-pair inner (K rows packed as pairs in kT columns)
        #pragma unroll 4
        for (int d = 0; d < DH; ++d) {
            const int hd = h * DH + d;
            float qd = qT[hd * PQ + ii];
            u64 q2 = pack2(qd, qd);
            const float* kc = &kT[hd * PQ];
            #pragma unroll
            for (int mp = 0; mp < 25; ++mp)
                sc2[mp] = fma2(q2, *(const u64*)&kc[2 * mp], sc2[mp]);
        }

        float sc[50];
        #pragma unroll
        for (int mp = 0; mp < 25; ++mp) unpack2(sc2[mp], sc[2 * mp], sc[2 * mp + 1]);

        const int w = b & (NWIN - 1);
        const float* ab = &g_abias[(((w * NH + h) * N_TOK) + ii) * N_TOK];
        #pragma unroll
        for (int m = 0; m < N_TOK; ++m) sc[m] += ab[m];
        sc[49] = -1e30f;

        float mx = sc[0];
        #pragma unroll
        for (int m = 1; m < N_TOK; ++m) mx = fmaxf(mx, sc[m]);
        float sum = 0.f;
        #pragma unroll
        for (int m = 0; m < 50; ++m) {
            float e = __expf(sc[m] - mx);
            sc[m] = e;
            sum += e;
        }
        const float inv = 1.f / sum;
        u64 p2[25];
        #pragma unroll
        for (int mp = 0; mp < 25; ++mp)
            p2[mp] = pack2(sc[2 * mp] * inv, sc[2 * mp + 1] * inv);

        // PV: d-outer, pair-inner; horizontal add per d; write to aoT (= xT buffer)
        float* aoT = xT;
        #pragma unroll 4
        for (int d = 0; d < DH; ++d) {
            const int hd = h * DH + d;
            const float* vc = &vT[hd * PQ];
            u64 a2 = pack2(0.f, 0.f);
            #pragma unroll
            for (int mp = 0; mp < 25; ++mp)
                a2 = fma2(p2[mp], *(const u64*)&vc[2 * mp], a2);
            float lo, hi; unpack2(a2, lo, hi);
            if (i < N_TOK) aoT[hd * PX + i] = lo + hi;
        }
    }
    __syncthreads();

    // ---------- Phase 5: out = ao @ proj_w + b  (2 cols x 5 row-pairs per thread) ----------
    {
        const float* aoT = xT;
        const int cg = tid & 63;          // 0..63 : cols 2*cg, 2*cg+1  (coalesced stores)
        const int rg = tid >> 6;          // 0..5  : row-pairs rg*5..rg*5+4 (warp-uniform)
        const int j0 = cg * 2;
        const int rb = rg * 10;

        u64 acc[2][5];
        #pragma unroll
        for (int c = 0; c < 2; ++c) {
            float pb = proj_b[j0 + c];
            u64 pb2 = pack2(pb, pb);
            #pragma unroll
            for (int p = 0; p < 5; ++p) acc[c][p] = pb2;
        }

        #pragma unroll 2
        for (int k = 0; k < CDIM; ++k) {
            const float2 w2 = *(const float2*)&proj_w[k * CDIM + j0];
            u64 wb0 = pack2(w2.x, w2.x);
            u64 wb1 = pack2(w2.y, w2.y);
            const float* ar = &aoT[k * PX + rb];
            u64 xp[5];
            #pragma unroll
            for (int p = 0; p < 5; ++p) xp[p] = *(const u64*)&ar[2 * p];
            #pragma unroll
            for (int p = 0; p < 5; ++p) {
                acc[0][p] = fma2(xp[p], wb0, acc[0][p]);
                acc[1][p] = fma2(xp[p], wb1, acc[1][p]);
            }
        }

        float* ob = out + (size_t)b * (N_TOK * CDIM);
        #pragma unroll
        for (int p = 0; p < 5; ++p) {
            int r0 = rb + 2 * p;
            #pragma unroll
            for (int c = 0; c < 2; ++c) {
                float lo, hi; unpack2(acc[c][p], lo, hi);
                if (r0 < N_TOK)     ob[r0 * CDIM + j0 + c]       = lo;
                if (r0 + 1 < N_TOK) ob[(r0 + 1) * CDIM + j0 + c] = hi;
            }
        }
    }
}

extern "C" void kernel_launch(void* const* d_in, const int* in_sizes, int n_in,
                              void* d_out, int out_size)
{
    const float* x          = (const float*)d_in[0];
    const float* mask       = (const float*)d_in[1];
    const float* qkv_w      = (const float*)d_in[2];
    const float* qkv_b      = (const float*)d_in[3];
    const float* proj_w     = (const float*)d_in[4];
    const float* proj_b     = (const float*)d_in[5];
    const float* bias_table = (const float*)d_in[6];
    const int*   rel_index  = (const int*)d_in[7];
    float* out = (float*)d_out;

    const int B = in_sizes[0] / (N_TOK * CDIM);   // 4096 windows

    // build fused bias+mask table (deterministic, rebuilt every call)
    {
        const int TOT = NWIN * NH * N_TOK * N_TOK;
        build_abias_kernel<<<(TOT + 255) / 256, 256>>>(mask, bias_table, rel_index);
    }

    const size_t shmem = SMEM_FLOATS * sizeof(float);   // ~117 KB
    cudaFuncSetAttribute(win_attn_kernel,
                         cudaFuncAttributeMaxDynamicSharedMemorySize, (int)shmem);
    win_attn_kernel<<<B, NTHREADS, shmem>>>(x, qkv_w, qkv_b, proj_w, proj_b, out);
}

// round 3
// speedup vs baseline: 1.7171x; 1.6160x over previous
#include <cuda_runtime.h>
#include <cuda_bf16.h>

#define N_TOK    49
#define CDIM     128
#define NH       4
#define DH       32
#define QKV_N    384
#define NWIN     64
#define NTHREADS 384
#define SCALE    0.17677669529663687f

// ---------------- smem layout (bytes) ----------------
#define PT        50                       // qT/kT/vT pitch (fp32 rows 0..49)
#define SM_QT     0
#define SM_KT     (SM_QT + 128*PT*4)       // 25600
#define SM_VT     (SM_KT + 128*PT*4)       // 51200
#define SM_R2     (SM_VT + 128*PT*4)       // 76800  (overlay region)
#define SM_XS     SM_R2                    // x staging 49*128*4 = 25088
#define SM_WCH    SM_R2                    // weight chunk hi: 4*48*32*2*4 = 49152
#define SM_WCL    (SM_WCH + 49152)         // 125952
#define SM_AOH    SM_R2                    // ao frag hi: 8*4*32*4*4 = 16384
#define SM_AOL    (SM_AOH + 16384)         // 93184
#define SM_PWH    (SM_AOL + 16384)         // 109568, proj w hi: 8*16*32*2*4 = 32768
#define SM_PWL    (SM_PWH + 32768)         // 142336
#define SM_XFH    (SM_WCL + 49152)         // 175104, x frag hi: 8*4*32*4*4 = 16384
#define SM_XFL    (SM_XFH + 16384)         // 191488
#define SMEM_BYTES (SM_XFL + 16384)        // 207872

typedef unsigned long long u64;
typedef unsigned int u32;

// ---------------- device globals ----------------
__device__ float g_abias[NWIN * NH * N_TOK * N_TOK];
__device__ u32 g_wqkvH[8 * 48 * 32 * 2];   // [k16][n8][lane][2]
__device__ u32 g_wqkvL[8 * 48 * 32 * 2];
__device__ u32 g_wprojH[8 * 16 * 32 * 2];
__device__ u32 g_wprojL[8 * 16 * 32 * 2];

// ---------------- helpers ----------------
__device__ __forceinline__ u64 pack2(float lo, float hi) {
    u64 r; asm("mov.b64 %0, {%1, %2};" : "=l"(r) : "f"(lo), "f"(hi)); return r;
}
__device__ __forceinline__ void unpack2(u64 v, float& lo, float& hi) {
    asm("mov.b64 {%0, %1}, %2;" : "=f"(lo), "=f"(hi) : "l"(v));
}
__device__ __forceinline__ u64 fma2(u64 a, u64 b, u64 c) {
    u64 d; asm("fma.rn.f32x2 %0, %1, %2, %3;" : "=l"(d) : "l"(a), "l"(b), "l"(c)); return d;
}

// bf16 split of (a,b): hi = packed bf16 high-parts (a in low half), lo = packed residuals
__device__ __forceinline__ void bsplit(float a, float b, u32& hi, u32& lo) {
    __nv_bfloat16 ah = __float2bfloat16(a), bh = __float2bfloat16(b);
    __nv_bfloat16 al = __float2bfloat16(a - __bfloat162float(ah));
    __nv_bfloat16 bl = __float2bfloat16(b - __bfloat162float(bh));
    hi = (u32)__bfloat16_as_ushort(ah) | ((u32)__bfloat16_as_ushort(bh) << 16);
    lo = (u32)__bfloat16_as_ushort(al) | ((u32)__bfloat16_as_ushort(bl) << 16);
}

__device__ __forceinline__ void mma_bf16(float c[4], const u32 a[4], const u32 b[2]) {
    asm volatile("mma.sync.aligned.m16n8k16.row.col.f32.bf16.bf16.f32 "
                 "{%0,%1,%2,%3}, {%4,%5,%6,%7}, {%8,%9}, {%0,%1,%2,%3};"
                 : "+f"(c[0]), "+f"(c[1]), "+f"(c[2]), "+f"(c[3])
                 : "r"(a[0]), "r"(a[1]), "r"(a[2]), "r"(a[3]), "r"(b[0]), "r"(b[1]));
}

// ---------------- prep kernels ----------------
__global__ void build_abias_kernel(const float* __restrict__ mask,
                                   const float* __restrict__ bias_table,
                                   const int*   __restrict__ rel_index)
{
    int idx = blockIdx.x * blockDim.x + threadIdx.x;
    const int TOT = NWIN * NH * N_TOK * N_TOK;
    if (idx >= TOT) return;
    int m = idx % N_TOK;
    int i = (idx / N_TOK) % N_TOK;
    int h = (idx / (N_TOK * N_TOK)) % NH;
    int w = idx / (NH * N_TOK * N_TOK);
    g_abias[idx] = bias_table[rel_index[i * N_TOK + m] * NH + h]
                 + mask[(w * N_TOK + i) * N_TOK + m];
}

// pack W[K x N] (row-major) into b-fragment layout [k16][n8][lane][2], hi/lo split
__global__ void pack_w_kernel(const float* __restrict__ W, u32* dH, u32* dL,
                              int N, int nn8, int total)
{
    int s = blockIdx.x * blockDim.x + threadIdx.x;
    if (s >= total) return;
    int ln  = s & 31;
    int n8  = (s >> 5) % nn8;
    int k16 = s / (nn8 * 32);
    int gg = ln >> 2, tt = ln & 3;
    int col = n8 * 8 + gg;
    int r = k16 * 16 + 2 * tt;
    float w0 = W[(r + 0) * N + col], w1 = W[(r + 1) * N + col];
    float w2 = W[(r + 8) * N + col], w3 = W[(r + 9) * N + col];
    u32 h0, l0, h1, l1;
    bsplit(w0, w1, h0, l0);
    bsplit(w2, w3, h1, l1);
    dH[s * 2] = h0; dH[s * 2 + 1] = h1;
    dL[s * 2] = l0; dL[s * 2 + 1] = l1;
}

// ---------------- main kernel ----------------
__global__ void __launch_bounds__(NTHREADS, 1)
win_attn_kernel(const float* __restrict__ x,
                const float* __restrict__ qkv_b,
                const float* __restrict__ proj_b,
                float* __restrict__ out)
{
    extern __shared__ char smem[];
    float* qT = (float*)(smem + SM_QT);
    float* kT = (float*)(smem + SM_KT);
    float* vT = (float*)(smem + SM_VT);

    const int b    = blockIdx.x;
    const int tid  = threadIdx.x;
    const int warp = tid >> 5;
    const int lane = tid & 31;
    const int g    = lane >> 2;
    const int tig  = lane & 3;

    // ---- P0: stage x window (coalesced) ----
    {
        float* xs = (float*)(smem + SM_XS);
        const float4* xb = (const float4*)(x + (size_t)b * (N_TOK * CDIM));
        for (int idx = tid; idx < (N_TOK * CDIM) / 4; idx += NTHREADS)
            ((float4*)xs)[idx] = xb[idx];
    }
    __syncthreads();

    // ---- P1: pack x into A-fragment layout (bf16 hi/lo), rows >=49 zero ----
    {
        const float* xs = (const float*)(smem + SM_XS);
        u32* xfH = (u32*)(smem + SM_XFH);
        u32* xfL = (u32*)(smem + SM_XFL);
        for (int s = tid; s < 1024; s += NTHREADS) {
            int k16 = s >> 7, m16 = (s >> 5) & 3, ln = s & 31;
            int gg = ln >> 2, tt = ln & 3;
            int r0 = m16 * 16 + gg, r1 = r0 + 8;
            int c0 = k16 * 16 + 2 * tt;
            float e0 = (r0 < N_TOK) ? xs[r0 * CDIM + c0]     : 0.f;
            float e1 = (r0 < N_TOK) ? xs[r0 * CDIM + c0 + 1] : 0.f;
            float e2 = (r1 < N_TOK) ? xs[r1 * CDIM + c0]     : 0.f;
            float e3 = (r1 < N_TOK) ? xs[r1 * CDIM + c0 + 1] : 0.f;
            float e4 = (r0 < N_TOK) ? xs[r0 * CDIM + c0 + 8] : 0.f;
            float e5 = (r0 < N_TOK) ? xs[r0 * CDIM + c0 + 9] : 0.f;
            float e6 = (r1 < N_TOK) ? xs[r1 * CDIM + c0 + 8] : 0.f;
            float e7 = (r1 < N_TOK) ? xs[r1 * CDIM + c0 + 9] : 0.f;
            u32 h[4], l[4];
            bsplit(e0, e1, h[0], l[0]);
            bsplit(e2, e3, h[1], l[1]);
            bsplit(e4, e5, h[2], l[2]);
            bsplit(e6, e7, h[3], l[3]);
            *(uint4*)&xfH[s * 4] = make_uint4(h[0], h[1], h[2], h[3]);
            *(uint4*)&xfL[s * 4] = make_uint4(l[0], l[1], l[2], l[3]);
        }
    }
    __syncthreads();

    // ---- P2: qkv = x @ W (bf16 3-term mma), 12 warps: warp = 32 rows x 64 cols ----
    {
        const int mw = warp & 1;          // 0..1 -> rows mw*32..mw*32+31
        const int nw = warp >> 1;         // 0..5 -> cols nw*64..nw*64+63
        const u32* xfH = (const u32*)(smem + SM_XFH);
        const u32* xfL = (const u32*)(smem + SM_XFL);

        float c[2][8][4];
        #pragma unroll
        for (int t = 0; t < 2; ++t)
            #pragma unroll
            for (int j = 0; j < 8; ++j)
                #pragma unroll
                for (int q = 0; q < 4; ++q) c[t][j][q] = 0.f;

        for (int kc = 0; kc < 2; ++kc) {
            // copy weight chunk (frag layout, straight memcpy)
            {
                const uint4* ghu = (const uint4*)(g_wqkvH + kc * 12288);
                const uint4* glu = (const uint4*)(g_wqkvL + kc * 12288);
                uint4* sh = (uint4*)(smem + SM_WCH);
                uint4* sl = (uint4*)(smem + SM_WCL);
                for (int idx = tid; idx < 3072; idx += NTHREADS) {
                    sh[idx] = ghu[idx];
                    sl[idx] = glu[idx];
                }
            }
            __syncthreads();

            #pragma unroll
            for (int kl = 0; kl < 4; ++kl) {
                const int k16 = kc * 4 + kl;
                u32 aH[2][4], aL[2][4];
                #pragma unroll
                for (int t = 0; t < 2; ++t) {
                    uint4 vh = *(const uint4*)&xfH[((k16 * 4 + 2 * mw + t) * 32 + lane) * 4];
                    uint4 vl = *(const uint4*)&xfL[((k16 * 4 + 2 * mw + t) * 32 + lane) * 4];
                    aH[t][0] = vh.x; aH[t][1] = vh.y; aH[t][2] = vh.z; aH[t][3] = vh.w;
                    aL[t][0] = vl.x; aL[t][1] = vl.y; aL[t][2] = vl.z; aL[t][3] = vl.w;
                }
                const u32* wch = (const u32*)(smem + SM_WCH) + kl * (48 * 32 * 2);
                const u32* wcl = (const u32*)(smem + SM_WCL) + kl * (48 * 32 * 2);
                #pragma unroll
                for (int j = 0; j < 8; ++j) {
                    const int n8 = nw * 8 + j;
                    uint2 bh2 = *(const uint2*)&wch[(n8 * 32 + lane) * 2];
                    uint2 bl2 = *(const uint2*)&wcl[(n8 * 32 + lane) * 2];
                    u32 bH[2] = {bh2.x, bh2.y};
                    u32 bL[2] = {bl2.x, bl2.y};
                    #pragma unroll
                    for (int t = 0; t < 2; ++t) {
                        mma_bf16(c[t][j], aH[t], bH);
                        mma_bf16(c[t][j], aH[t], bL);
                        mma_bf16(c[t][j], aL[t], bH);
                    }
                }
            }
            __syncthreads();
        }

        // epilogue: scatter to qT/kT/vT (+bias, q*SCALE)
        float* dstT;
        int cb;
        if (nw < 2)      { dstT = qT; cb = nw * 64; }
        else if (nw < 4) { dstT = kT; cb = (nw - 2) * 64; }
        else             { dstT = vT; cb = (nw - 4) * 64; }
        const bool isq = (nw < 2);
        #pragma unroll
        for (int t = 0; t < 2; ++t) {
            const int r0 = mw * 32 + t * 16 + g;
            const int r1 = r0 + 8;
            #pragma unroll
            for (int j = 0; j < 8; ++j) {
                const int col0 = cb + j * 8 + 2 * tig;
                const int gcol = nw * 64 + j * 8 + 2 * tig;
                const float b0 = qkv_b[gcol], b1 = qkv_b[gcol + 1];
                float v00 = c[t][j][0] + b0, v01 = c[t][j][1] + b1;
                float v10 = c[t][j][2] + b0, v11 = c[t][j][3] + b1;
                if (isq) { v00 *= SCALE; v01 *= SCALE; v10 *= SCALE; v11 *= SCALE; }
                if (r0 < 50) { dstT[col0 * PT + r0] = v00; dstT[(col0 + 1) * PT + r0] = v01; }
                if (r1 < 50) { dstT[col0 * PT + r1] = v10; dstT[(col0 + 1) * PT + r1] = v11; }
            }
        }
    }
    __syncthreads();

    // ---- P3: attention (warps 0-7 scalar) + proj-weight prefetch (warps 8-11) ----
    if (tid >= 256) {
        const uint4* ghu = (const uint4*)g_wprojH;
        const uint4* glu = (const uint4*)g_wprojL;
        uint4* sh = (uint4*)(smem + SM_PWH);
        uint4* sl = (uint4*)(smem + SM_PWL);
        for (int idx = tid - 256; idx < 2048; idx += 128) {
            sh[idx] = ghu[idx];
            sl[idx] = glu[idx];
        }
    } else {
        const int h  = tid >> 6;
        const int i  = tid & 63;
        const int ii = (i < N_TOK) ? i : (N_TOK - 1);

        u64 sc2[25];
        #pragma unroll
        for (int mp = 0; mp < 25; ++mp) sc2[mp] = pack2(0.f, 0.f);

        #pragma unroll 4
        for (int d = 0; d < DH; ++d) {
            const int hd = h * DH + d;
            float qd = qT[hd * PT + ii];
            u64 q2 = pack2(qd, qd);
            const float* kc = &kT[hd * PT];
            #pragma unroll
            for (int mp = 0; mp < 25; ++mp)
                sc2[mp] = fma2(q2, *(const u64*)&kc[2 * mp], sc2[mp]);
        }

        float sc[50];
        #pragma unroll
        for (int mp = 0; mp < 25; ++mp) unpack2(sc2[mp], sc[2 * mp], sc[2 * mp + 1]);

        const int w = b & (NWIN - 1);
        const float* ab = &g_abias[(((w * NH + h) * N_TOK) + ii) * N_TOK];
        #pragma unroll
        for (int m = 0; m < N_TOK; ++m) sc[m] += ab[m];
        sc[49] = -1e30f;

        float mx = sc[0];
        #pragma unroll
        for (int m = 1; m < N_TOK; ++m) mx = fmaxf(mx, sc[m]);
        float sum = 0.f;
        #pragma unroll
        for (int m = 0; m < 50; ++m) {
            float e = __expf(sc[m] - mx);
            sc[m] = e;
            sum += e;
        }
        const float inv = 1.f / sum;
        u64 p2[25];
        #pragma unroll
        for (int mp = 0; mp < 25; ++mp)
            p2[mp] = pack2(sc[2 * mp] * inv, sc[2 * mp + 1] * inv);

        float aov[DH];
        #pragma unroll 4
        for (int d = 0; d < DH; ++d) {
            const int hd = h * DH + d;
            const float* vc = &vT[hd * PT];
            u64 a2 = pack2(0.f, 0.f);
            #pragma unroll
            for (int mp = 0; mp < 25; ++mp)
                a2 = fma2(p2[mp], *(const u64*)&vc[2 * mp], a2);
            float lo, hi; unpack2(a2, lo, hi);
            aov[d] = lo + hi;
        }

        // write ao into A-fragment layout (bf16 hi/lo)
        if (i < N_TOK) {
            u32* aoH = (u32*)(smem + SM_AOH);
            u32* aoL = (u32*)(smem + SM_AOL);
            const int mt = i >> 4;
            const int lnbase = (i & 7) * 4;
            const int regm = (i >> 3) & 1;
            #pragma unroll
            for (int d = 0; d < DH; d += 2) {
                const int c0 = h * DH + d;
                const int k16 = c0 >> 4;
                const int ln  = lnbase + ((c0 & 7) >> 1);
                const int reg = regm + 2 * ((c0 >> 3) & 1);
                u32 hi, lo;
                bsplit(aov[d], aov[d + 1], hi, lo);
                const int off = ((k16 * 4 + mt) * 32 + ln) * 4 + reg;
                aoH[off] = hi;
                aoL[off] = lo;
            }
        }
    }
    __syncthreads();

    // ---- P4: out = ao @ proj_w + b (8 warps: warp = 16 rows x 64 cols) ----
    if (tid < 256) {
        const int mw  = warp & 3;
        const int nw2 = warp >> 2;
        const u32* aoH = (const u32*)(smem + SM_AOH);
        const u32* aoL = (const u32*)(smem + SM_AOL);
        const u32* pwH = (const u32*)(smem + SM_PWH);
        const u32* pwL = (const u32*)(smem + SM_PWL);

        float c[8][4];
        #pragma unroll
        for (int j = 0; j < 8; ++j)
            #pragma unroll
            for (int q = 0; q < 4; ++q) c[j][q] = 0.f;

        #pragma unroll
        for (int k16 = 0; k16 < 8; ++k16) {
            u32 aH[4], aL[4];
            uint4 vh = *(const uint4*)&aoH[((k16 * 4 + mw) * 32 + lane) * 4];
            uint4 vl = *(const uint4*)&aoL[((k16 * 4 + mw) * 32 + lane) * 4];
            aH[0] = vh.x; aH[1] = vh.y; aH[2] = vh.z; aH[3] = vh.w;
            aL[0] = vl.x; aL[1] = vl.y; aL[2] = vl.z; aL[3] = vl.w;
            #pragma unroll
            for (int j = 0; j < 8; ++j) {
                const int n8 = nw2 * 8 + j;
                uint2 bh2 = *(const uint2*)&pwH[((k16 * 16 + n8) * 32 + lane) * 2];
                uint2 bl2 = *(const uint2*)&pwL[((k16 * 16 + n8) * 32 + lane) * 2];
                u32 bH[2] = {bh2.x, bh2.y};
                u32 bL[2] = {bl2.x, bl2.y};
                mma_bf16(c[j], aH, bH);
                mma_bf16(c[j], aH, bL);
                mma_bf16(c[j], aL, bH);
            }
        }

        float* ob = out + (size_t)b * (N_TOK * CDIM);
        const int r0 = mw * 16 + g;
        const int r1 = r0 + 8;
        #pragma unroll
        for (int j = 0; j < 8; ++j) {
            const int col = nw2 * 64 + j * 8 + 2 * tig;
            const float b0 = proj_b[col], b1 = proj_b[col + 1];
            if (r0 < N_TOK)
                *(float2*)&ob[r0 * CDIM + col] = make_float2(c[j][0] + b0, c[j][1] + b1);
            if (r1 < N_TOK)
                *(float2*)&ob[r1 * CDIM + col] = make_float2(c[j][2] + b0, c[j][3] + b1);
        }
    }
}

extern "C" void kernel_launch(void* const* d_in, const int* in_sizes, int n_in,
                              void* d_out, int out_size)
{
    const float* x          = (const float*)d_in[0];
    const float* mask       = (const float*)d_in[1];
    const float* qkv_w      = (const float*)d_in[2];
    const float* qkv_b      = (const float*)d_in[3];
    const float* proj_w     = (const float*)d_in[4];
    const float* proj_b     = (const float*)d_in[5];
    const float* bias_table = (const float*)d_in[6];
    const int*   rel_index  = (const int*)d_in[7];
    float* out = (float*)d_out;

    const int B = in_sizes[0] / (N_TOK * CDIM);

    {
        const int TOT = NWIN * NH * N_TOK * N_TOK;
        build_abias_kernel<<<(TOT + 255) / 256, 256>>>(mask, bias_table, rel_index);
    }
    {
        u32 *dH, *dL;
        cudaGetSymbolAddress((void**)&dH, g_wqkvH);
        cudaGetSymbolAddress((void**)&dL, g_wqkvL);
        pack_w_kernel<<<(8 * 48 * 32 + 255) / 256, 256>>>(qkv_w, dH, dL, QKV_N, 48, 8 * 48 * 32);
        cudaGetSymbolAddress((void**)&dH, g_wprojH);
        cudaGetSymbolAddress((void**)&dL, g_wprojL);
        pack_w_kernel<<<(8 * 16 * 32 + 255) / 256, 256>>>(proj_w, dH, dL, CDIM, 16, 8 * 16 * 32);
    }

    cudaFuncSetAttribute(win_attn_kernel,
                         cudaFuncAttributeMaxDynamicSharedMemorySize, SMEM_BYTES);
    win_attn_kernel<<<B, NTHREADS, SMEM_BYTES>>>(x, qkv_b, proj_b, out);
}

// round 4
// speedup vs baseline: 2.0664x; 1.2035x over previous
#include <cuda_runtime.h>
#include <cuda_bf16.h>

#define N_TOK    49
#define CDIM     128
#define NH       4
#define DH       32
#define QKV_N    384
#define NWIN     64
#define NTHREADS 384
#define SCALE    0.17677669529663687f

#define PT       52                        // qT/kT/vT pitch -> conflict-free epilogue
#define SM_QT    0
#define SM_KT    (SM_QT + 128*PT*4)        // 26624
#define SM_VT    (SM_KT + 128*PT*4)        // 53248
#define SM_FR    (SM_VT + 128*PT*4)        // 79872 : xf (P0-P2) / ao (P3-P4) overlay
#define SM_FRH   SM_FR
#define SM_FRL   (SM_FR + 16384)
#define SMEM_BYTES (SM_FR + 32768)         // 112640

typedef unsigned long long u64;
typedef unsigned int u32;

// ---------------- device globals ----------------
__device__ float g_abiasT[NWIN * NH * N_TOK * 64];   // [w][h][m][i], pitch 64
__device__ u32 g_wqkvH[8 * 48 * 32 * 2];             // [k16][n8][lane][2]
__device__ u32 g_wqkvL[8 * 48 * 32 * 2];
__device__ u32 g_wprojH[8 * 16 * 32 * 2];
__device__ u32 g_wprojL[8 * 16 * 32 * 2];

// ---------------- helpers ----------------
__device__ __forceinline__ u64 pack2(float lo, float hi) {
    u64 r; asm("mov.b64 %0, {%1, %2};" : "=l"(r) : "f"(lo), "f"(hi)); return r;
}
__device__ __forceinline__ void unpack2(u64 v, float& lo, float& hi) {
    asm("mov.b64 {%0, %1}, %2;" : "=f"(lo), "=f"(hi) : "l"(v));
}
__device__ __forceinline__ u64 fma2(u64 a, u64 b, u64 c) {
    u64 d; asm("fma.rn.f32x2 %0, %1, %2, %3;" : "=l"(d) : "l"(a), "l"(b), "l"(c)); return d;
}
__device__ __forceinline__ void bsplit(float a, float b, u32& hi, u32& lo) {
    __nv_bfloat16 ah = __float2bfloat16(a), bh = __float2bfloat16(b);
    __nv_bfloat16 al = __float2bfloat16(a - __bfloat162float(ah));
    __nv_bfloat16 bl = __float2bfloat16(b - __bfloat162float(bh));
    hi = (u32)__bfloat16_as_ushort(ah) | ((u32)__bfloat16_as_ushort(bh) << 16);
    lo = (u32)__bfloat16_as_ushort(al) | ((u32)__bfloat16_as_ushort(bl) << 16);
}
__device__ __forceinline__ void mma_bf16(float c[4], const u32 a[4], const u32 b[2]) {
    asm volatile("mma.sync.aligned.m16n8k16.row.col.f32.bf16.bf16.f32 "
                 "{%0,%1,%2,%3}, {%4,%5,%6,%7}, {%8,%9}, {%0,%1,%2,%3};"
                 : "+f"(c[0]), "+f"(c[1]), "+f"(c[2]), "+f"(c[3])
                 : "r"(a[0]), "r"(a[1]), "r"(a[2]), "r"(a[3]), "r"(b[0]), "r"(b[1]));
}

// ---------------- prep kernels ----------------
__global__ void build_abias_kernel(const float* __restrict__ mask,
                                   const float* __restrict__ bias_table,
                                   const int*   __restrict__ rel_index)
{
    int idx = blockIdx.x * blockDim.x + threadIdx.x;
    const int TOT = NWIN * NH * N_TOK * 64;
    if (idx >= TOT) return;
    int i = idx & 63;
    int m = (idx >> 6) % N_TOK;
    int h = (idx / (64 * N_TOK)) % NH;
    int w = idx / (NH * N_TOK * 64);
    float v = 0.f;
    if (i < N_TOK)
        v = bias_table[rel_index[i * N_TOK + m] * NH + h]
          + mask[(w * N_TOK + i) * N_TOK + m];
    g_abiasT[idx] = v;
}

__global__ void pack_w_kernel(const float* __restrict__ W, u32* dH, u32* dL,
                              int N, int nn8, int total)
{
    int s = blockIdx.x * blockDim.x + threadIdx.x;
    if (s >= total) return;
    int ln  = s & 31;
    int n8  = (s >> 5) % nn8;
    int k16 = s / (nn8 * 32);
    int gg = ln >> 2, tt = ln & 3;
    int col = n8 * 8 + gg;
    int r = k16 * 16 + 2 * tt;
    float w0 = W[(r + 0) * N + col], w1 = W[(r + 1) * N + col];
    float w2 = W[(r + 8) * N + col], w3 = W[(r + 9) * N + col];
    u32 h0, l0, h1, l1;
    bsplit(w0, w1, h0, l0);
    bsplit(w2, w3, h1, l1);
    dH[s * 2] = h0; dH[s * 2 + 1] = h1;
    dL[s * 2] = l0; dL[s * 2 + 1] = l1;
}

// ---------------- main kernel ----------------
__global__ void __launch_bounds__(NTHREADS, 1)
win_attn_kernel(const float* __restrict__ x,
                const float* __restrict__ qkv_b,
                const float* __restrict__ proj_b,
                float* __restrict__ out)
{
    extern __shared__ char smem[];
    float* qT = (float*)(smem + SM_QT);
    float* kT = (float*)(smem + SM_KT);
    float* vT = (float*)(smem + SM_VT);

    const int b    = blockIdx.x;
    const int tid  = threadIdx.x;
    const int warp = tid >> 5;
    const int lane = tid & 31;
    const int g    = lane >> 2;
    const int tig  = lane & 3;

    // ---- P0: pack x fragments directly from global (bf16 hi/lo) ----
    {
        const float* xb = x + (size_t)b * (N_TOK * CDIM);
        u32* xfH = (u32*)(smem + SM_FRH);
        u32* xfL = (u32*)(smem + SM_FRL);
        for (int s = tid; s < 1024; s += NTHREADS) {
            int k16 = s >> 7, m16 = (s >> 5) & 3, ln = s & 31;
            int gg = ln >> 2, tt = ln & 3;
            int r0 = m16 * 16 + gg, r1 = r0 + 8;
            int c0 = k16 * 16 + 2 * tt;
            float2 p00 = (r0 < N_TOK) ? *(const float2*)&xb[r0 * CDIM + c0]     : make_float2(0.f, 0.f);
            float2 p10 = (r1 < N_TOK) ? *(const float2*)&xb[r1 * CDIM + c0]     : make_float2(0.f, 0.f);
            float2 p01 = (r0 < N_TOK) ? *(const float2*)&xb[r0 * CDIM + c0 + 8] : make_float2(0.f, 0.f);
            float2 p11 = (r1 < N_TOK) ? *(const float2*)&xb[r1 * CDIM + c0 + 8] : make_float2(0.f, 0.f);
            u32 h[4], l[4];
            bsplit(p00.x, p00.y, h[0], l[0]);
            bsplit(p10.x, p10.y, h[1], l[1]);
            bsplit(p01.x, p01.y, h[2], l[2]);
            bsplit(p11.x, p11.y, h[3], l[3]);
            *(uint4*)&xfH[s * 4] = make_uint4(h[0], h[1], h[2], h[3]);
            *(uint4*)&xfL[s * 4] = make_uint4(l[0], l[1], l[2], l[3]);
        }
    }
    __syncthreads();

    // ---- P2: qkv = x @ W, B-fragments streamed from L2 with register double-buffer ----
    {
        const int mw = warp & 1;          // rows mw*32..+31
        const int nw = warp >> 1;         // cols nw*64..+63
        const u32* xfH = (const u32*)(smem + SM_FRH);
        const u32* xfL = (const u32*)(smem + SM_FRL);

        float c[2][8][4];
        #pragma unroll
        for (int t = 0; t < 2; ++t)
            #pragma unroll
            for (int j = 0; j < 8; ++j)
                #pragma unroll
                for (int q = 0; q < 4; ++q) c[t][j][q] = 0.f;

        u32 bh[2][8][2], bl[2][8][2];
        // prefetch k16=0
        #pragma unroll
        for (int j = 0; j < 8; ++j) {
            const int off = ((0 * 48 + nw * 8 + j) * 32 + lane) * 2;
            *(uint2*)bh[0][j] = *(const uint2*)&g_wqkvH[off];
            *(uint2*)bl[0][j] = *(const uint2*)&g_wqkvL[off];
        }

        #pragma unroll
        for (int k16 = 0; k16 < 8; ++k16) {
            const int cur = k16 & 1, nxt = cur ^ 1;
            if (k16 < 7) {
                #pragma unroll
                for (int j = 0; j < 8; ++j) {
                    const int off = (((k16 + 1) * 48 + nw * 8 + j) * 32 + lane) * 2;
                    *(uint2*)bh[nxt][j] = *(const uint2*)&g_wqkvH[off];
                    *(uint2*)bl[nxt][j] = *(const uint2*)&g_wqkvL[off];
                }
            }
            u32 aH[2][4], aL[2][4];
            #pragma unroll
            for (int t = 0; t < 2; ++t) {
                uint4 vh = *(const uint4*)&xfH[((k16 * 4 + 2 * mw + t) * 32 + lane) * 4];
                uint4 vl = *(const uint4*)&xfL[((k16 * 4 + 2 * mw + t) * 32 + lane) * 4];
                aH[t][0] = vh.x; aH[t][1] = vh.y; aH[t][2] = vh.z; aH[t][3] = vh.w;
                aL[t][0] = vl.x; aL[t][1] = vl.y; aL[t][2] = vl.z; aL[t][3] = vl.w;
            }
            #pragma unroll
            for (int j = 0; j < 8; ++j) {
                #pragma unroll
                for (int t = 0; t < 2; ++t) {
                    mma_bf16(c[t][j], aH[t], bh[cur][j]);
                    mma_bf16(c[t][j], aH[t], bl[cur][j]);
                    mma_bf16(c[t][j], aL[t], bh[cur][j]);
                }
            }
        }
        __syncthreads();   // xf region about to be reused (ao) only after P3; safe: attention waits on qkv below

        // epilogue: scatter to qT/kT/vT (+bias, q*SCALE); PT=52 -> conflict-free
        float* dstT;
        int cb;
        if (nw < 2)      { dstT = qT; cb = nw * 64; }
        else if (nw < 4) { dstT = kT; cb = (nw - 2) * 64; }
        else             { dstT = vT; cb = (nw - 4) * 64; }
        const bool isq = (nw < 2);
        #pragma unroll
        for (int t = 0; t < 2; ++t) {
            const int r0 = mw * 32 + t * 16 + g;
            const int r1 = r0 + 8;
            #pragma unroll
            for (int j = 0; j < 8; ++j) {
                const int col0 = cb + j * 8 + 2 * tig;
                const int gcol = nw * 64 + j * 8 + 2 * tig;
                const float b0 = qkv_b[gcol], b1 = qkv_b[gcol + 1];
                float v00 = c[t][j][0] + b0, v01 = c[t][j][1] + b1;
                float v10 = c[t][j][2] + b0, v11 = c[t][j][3] + b1;
                if (isq) { v00 *= SCALE; v01 *= SCALE; v10 *= SCALE; v11 *= SCALE; }
                if (r0 < 50) { dstT[col0 * PT + r0] = v00; dstT[(col0 + 1) * PT + r0] = v01; }
                if (r1 < 50) { dstT[col0 * PT + r1] = v10; dstT[(col0 + 1) * PT + r1] = v11; }
            }
        }
    }
    __syncthreads();

    // ---- P3: attention (warps 0-7), vectorized LDS.128 K/V reads ----
    if (tid < 256) {
        const int h  = tid >> 6;
        const int i  = tid & 63;
        const int ii = (i < N_TOK) ? i : (N_TOK - 1);

        u64 sc2[25];
        const u64 z2 = pack2(0.f, 0.f);
        #pragma unroll
        for (int mp = 0; mp < 25; ++mp) sc2[mp] = z2;

        #pragma unroll 4
        for (int d = 0; d < DH; ++d) {
            const int hd = h * DH + d;
            float qd = qT[hd * PT + ii];
            u64 q2 = pack2(qd, qd);
            const ulonglong2* kc = (const ulonglong2*)&kT[hd * PT];
            #pragma unroll
            for (int mq = 0; mq < 12; ++mq) {
                ulonglong2 kk = kc[mq];
                sc2[2 * mq]     = fma2(q2, kk.x, sc2[2 * mq]);
                sc2[2 * mq + 1] = fma2(q2, kk.y, sc2[2 * mq + 1]);
            }
            sc2[24] = fma2(q2, *(const u64*)&kT[hd * PT + 48], sc2[24]);
        }

        float sc[50];
        #pragma unroll
        for (int mp = 0; mp < 25; ++mp) unpack2(sc2[mp], sc[2 * mp], sc[2 * mp + 1]);

        const int w = b & (NWIN - 1);
        const float* ab = &g_abiasT[((w * NH + h) * N_TOK) * 64 + ii];
        #pragma unroll
        for (int m = 0; m < N_TOK; ++m) sc[m] += ab[m * 64];
        sc[49] = -1e30f;

        float mx = sc[0];
        #pragma unroll
        for (int m = 1; m < N_TOK; ++m) mx = fmaxf(mx, sc[m]);
        float sum = 0.f;
        #pragma unroll
        for (int m = 0; m < 50; ++m) {
            float e = __expf(sc[m] - mx);
            sc[m] = e;
            sum += e;
        }
        const float inv = 1.f / sum;
        u64 p2[25];
        #pragma unroll
        for (int mp = 0; mp < 25; ++mp)
            p2[mp] = pack2(sc[2 * mp] * inv, sc[2 * mp + 1] * inv);

        float aov[DH];
        #pragma unroll 4
        for (int d = 0; d < DH; ++d) {
            const int hd = h * DH + d;
            const ulonglong2* vc = (const ulonglong2*)&vT[hd * PT];
            u64 a0 = z2, a1 = z2;
            #pragma unroll
            for (int mq = 0; mq < 12; ++mq) {
                ulonglong2 vv = vc[mq];
                a0 = fma2(p2[2 * mq],     vv.x, a0);
                a1 = fma2(p2[2 * mq + 1], vv.y, a1);
            }
            a0 = fma2(p2[24], *(const u64*)&vT[hd * PT + 48], a0);
            float l0, h0, l1, h1;
            unpack2(a0, l0, h0);
            unpack2(a1, l1, h1);
            aov[d] = (l0 + h0) + (l1 + h1);
        }

        // write ao into A-fragment layout (bf16 hi/lo) in overlay region
        if (i < N_TOK) {
            u32* aoH = (u32*)(smem + SM_FRH);
            u32* aoL = (u32*)(smem + SM_FRL);
            const int mt = i >> 4;
            const int lnbase = (i & 7) * 4;
            const int regm = (i >> 3) & 1;
            #pragma unroll
            for (int d = 0; d < DH; d += 2) {
                const int c0 = h * DH + d;
                const int k16 = c0 >> 4;
                const int ln  = lnbase + ((c0 & 7) >> 1);
                const int reg = regm + 2 * ((c0 >> 3) & 1);
                u32 hi, lo;
                bsplit(aov[d], aov[d + 1], hi, lo);
                const int off = ((k16 * 4 + mt) * 32 + ln) * 4 + reg;
                aoH[off] = hi;
                aoL[off] = lo;
            }
        }
    }
    __syncthreads();

    // ---- P4: out = ao @ proj_w + b (warps 0-7), B-fragments from L2 ----
    if (tid < 256) {
        const int mw  = warp & 3;
        const int nw2 = warp >> 2;
        const u32* aoH = (const u32*)(smem + SM_FRH);
        const u32* aoL = (const u32*)(smem + SM_FRL);

        float c[8][4];
        #pragma unroll
        for (int j = 0; j < 8; ++j)
            #pragma unroll
            for (int q = 0; q < 4; ++q) c[j][q] = 0.f;

        u32 bh[2][8][2], bl[2][8][2];
        #pragma unroll
        for (int j = 0; j < 8; ++j) {
            const int off = ((0 * 16 + nw2 * 8 + j) * 32 + lane) * 2;
            *(uint2*)bh[0][j] = *(const uint2*)&g_wprojH[off];
            *(uint2*)bl[0][j] = *(const uint2*)&g_wprojL[off];
        }

        #pragma unroll
        for (int k16 = 0; k16 < 8; ++k16) {
            const int cur = k16 & 1, nxt = cur ^ 1;
            if (k16 < 7) {
                #pragma unroll
                for (int j = 0; j < 8; ++j) {
                    const int off = (((k16 + 1) * 16 + nw2 * 8 + j) * 32 + lane) * 2;
                    *(uint2*)bh[nxt][j] = *(const uint2*)&g_wprojH[off];
                    *(uint2*)bl[nxt][j] = *(const uint2*)&g_wprojL[off];
                }
            }
            u32 aH[4], aL[4];
            uint4 vh = *(const uint4*)&aoH[((k16 * 4 + mw) * 32 + lane) * 4];
            uint4 vl = *(const uint4*)&aoL[((k16 * 4 + mw) * 32 + lane) * 4];
            aH[0] = vh.x; aH[1] = vh.y; aH[2] = vh.z; aH[3] = vh.w;
            aL[0] = vl.x; aL[1] = vl.y; aL[2] = vl.z; aL[3] = vl.w;
            #pragma unroll
            for (int j = 0; j < 8; ++j) {
                mma_bf16(c[j], aH, bh[cur][j]);
                mma_bf16(c[j], aH, bl[cur][j]);
                mma_bf16(c[j], aL, bh[cur][j]);
            }
        }

        float* ob = out + (size_t)b * (N_TOK * CDIM);
        const int r0 = mw * 16 + g;
        const int r1 = r0 + 8;
        #pragma unroll
        for (int j = 0; j < 8; ++j) {
            const int col = nw2 * 64 + j * 8 + 2 * tig;
            const float b0 = proj_b[col], b1 = proj_b[col + 1];
            if (r0 < N_TOK)
                *(float2*)&ob[r0 * CDIM + col] = make_float2(c[j][0] + b0, c[j][1] + b1);
            if (r1 < N_TOK)
                *(float2*)&ob[r1 * CDIM + col] = make_float2(c[j][2] + b0, c[j][3] + b1);
        }
    }
}

extern "C" void kernel_launch(void* const* d_in, const int* in_sizes, int n_in,
                              void* d_out, int out_size)
{
    const float* x          = (const float*)d_in[0];
    const float* mask       = (const float*)d_in[1];
    const float* qkv_w      = (const float*)d_in[2];
    const float* qkv_b      = (const float*)d_in[3];
    const float* proj_w     = (const float*)d_in[4];
    const float* proj_b     = (const float*)d_in[5];
    const float* bias_table = (const float*)d_in[6];
    const int*   rel_index  = (const int*)d_in[7];
    float* out = (float*)d_out;

    const int B = in_sizes[0] / (N_TOK * CDIM);

    {
        const int TOT = NWIN * NH * N_TOK * 64;
        build_abias_kernel<<<(TOT + 255) / 256, 256>>>(mask, bias_table, rel_index);
    }
    {
        u32 *dH, *dL;
        cudaGetSymbolAddress((void**)&dH, g_wqkvH);
        cudaGetSymbolAddress((void**)&dL, g_wqkvL);
        pack_w_kernel<<<(8 * 48 * 32 + 255) / 256, 256>>>(qkv_w, dH, dL, QKV_N, 48, 8 * 48 * 32);
        cudaGetSymbolAddress((void**)&dH, g_wprojH);
        cudaGetSymbolAddress((void**)&dL, g_wprojL);
        pack_w_kernel<<<(8 * 16 * 32 + 255) / 256, 256>>>(proj_w, dH, dL, CDIM, 16, 8 * 16 * 32);
    }

    cudaFuncSetAttribute(win_attn_kernel,
                         cudaFuncAttributeMaxDynamicSharedMemorySize, SMEM_BYTES);
    win_attn_kernel<<<B, NTHREADS, SMEM_BYTES>>>(x, qkv_b, proj_b, out);
}

// round 5
// speedup vs baseline: 2.1091x; 1.0206x over previous
#include <cuda_runtime.h>
#include <cuda_bf16.h>

#define N_TOK    49
#define CDIM     128
#define NH       4
#define DH       32
#define QKV_N    384
#define NWIN     64
#define NTHREADS 384
#define SCALE    0.17677669529663687f

#define PT       52
// ---- smem layout (bytes) ----
#define SM_QT    0
#define SM_KT    (SM_QT + 128*PT*4)        // 26624
#define SM_VT    (SM_KT + 128*PT*4)        // 53248
#define SM_FRH   (SM_VT + 128*PT*4)        // 79872  xf/ao hi
#define SM_FRL   (SM_FRH + 16384)          // 96256  xf/ao lo
#define SM_WRING (SM_FRL + 16384)          // 112640 2 stages x 24576
#define SM_PWH   (SM_WRING + 49152)        // 161792 proj w hi
#define SM_PWL   (SM_PWH + 32768)          // 194560 proj w lo
#define SMEM_BYTES (SM_PWL + 32768)        // 227328

typedef unsigned long long u64;
typedef unsigned int u32;

// ---------------- device globals ----------------
__device__ float g_abiasT[NWIN * NH * N_TOK * 64];   // [w][h][m][i], pitch 64
__device__ u32 g_wqkvH[8 * 48 * 32 * 2];             // [k16][n8][lane][2]
__device__ u32 g_wqkvL[8 * 48 * 32 * 2];
__device__ u32 g_wprojH[8 * 16 * 32 * 2];
__device__ u32 g_wprojL[8 * 16 * 32 * 2];

// ---------------- helpers ----------------
__device__ __forceinline__ u64 pack2(float lo, float hi) {
    u64 r; asm("mov.b64 %0, {%1, %2};" : "=l"(r) : "f"(lo), "f"(hi)); return r;
}
__device__ __forceinline__ void unpack2(u64 v, float& lo, float& hi) {
    asm("mov.b64 {%0, %1}, %2;" : "=f"(lo), "=f"(hi) : "l"(v));
}
__device__ __forceinline__ u64 fma2(u64 a, u64 b, u64 c) {
    u64 d; asm("fma.rn.f32x2 %0, %1, %2, %3;" : "=l"(d) : "l"(a), "l"(b), "l"(c)); return d;
}
__device__ __forceinline__ void bsplit(float a, float b, u32& hi, u32& lo) {
    __nv_bfloat16 ah = __float2bfloat16(a), bh = __float2bfloat16(b);
    __nv_bfloat16 al = __float2bfloat16(a - __bfloat162float(ah));
    __nv_bfloat16 bl = __float2bfloat16(b - __bfloat162float(bh));
    hi = (u32)__bfloat16_as_ushort(ah) | ((u32)__bfloat16_as_ushort(bh) << 16);
    lo = (u32)__bfloat16_as_ushort(al) | ((u32)__bfloat16_as_ushort(bl) << 16);
}
__device__ __forceinline__ void mma_bf16(float c[4], const u32 a[4], const u32 b[2]) {
    asm volatile("mma.sync.aligned.m16n8k16.row.col.f32.bf16.bf16.f32 "
                 "{%0,%1,%2,%3}, {%4,%5,%6,%7}, {%8,%9}, {%0,%1,%2,%3};"
                 : "+f"(c[0]), "+f"(c[1]), "+f"(c[2]), "+f"(c[3])
                 : "r"(a[0]), "r"(a[1]), "r"(a[2]), "r"(a[3]), "r"(b[0]), "r"(b[1]));
}
__device__ __forceinline__ void cp16(u32 daddr, const void* src) {
    asm volatile("cp.async.cg.shared.global [%0], [%1], 16;" :: "r"(daddr), "l"(src));
}
__device__ __forceinline__ void cp_commit() {
    asm volatile("cp.async.commit_group;");
}
template <int N> __device__ __forceinline__ void cp_wait() {
    asm volatile("cp.async.wait_group %0;" :: "n"(N));
}

// ---------------- prep kernels ----------------
__global__ void build_abias_kernel(const float* __restrict__ mask,
                                   const float* __restrict__ bias_table,
                                   const int*   __restrict__ rel_index)
{
    int idx = blockIdx.x * blockDim.x + threadIdx.x;
    const int TOT = NWIN * NH * N_TOK * 64;
    if (idx >= TOT) return;
    int i = idx & 63;
    int m = (idx >> 6) % N_TOK;
    int h = (idx / (64 * N_TOK)) % NH;
    int w = idx / (NH * N_TOK * 64);
    float v = 0.f;
    if (i < N_TOK)
        v = bias_table[rel_index[i * N_TOK + m] * NH + h]
          + mask[(w * N_TOK + i) * N_TOK + m];
    g_abiasT[idx] = v;
}

__global__ void pack_w_kernel(const float* __restrict__ W, u32* dH, u32* dL,
                              int N, int nn8, int total)
{
    int s = blockIdx.x * blockDim.x + threadIdx.x;
    if (s >= total) return;
    int ln  = s & 31;
    int n8  = (s >> 5) % nn8;
    int k16 = s / (nn8 * 32);
    int gg = ln >> 2, tt = ln & 3;
    int col = n8 * 8 + gg;
    int r = k16 * 16 + 2 * tt;
    float w0 = W[(r + 0) * N + col], w1 = W[(r + 1) * N + col];
    float w2 = W[(r + 8) * N + col], w3 = W[(r + 9) * N + col];
    u32 h0, l0, h1, l1;
    bsplit(w0, w1, h0, l0);
    bsplit(w2, w3, h1, l1);
    dH[s * 2] = h0; dH[s * 2 + 1] = h1;
    dL[s * 2] = l0; dL[s * 2 + 1] = l1;
}

// ---------------- main kernel ----------------
__global__ void __launch_bounds__(NTHREADS, 1)
win_attn_kernel(const float* __restrict__ x,
                const float* __restrict__ qkv_b,
                const float* __restrict__ proj_b,
                float* __restrict__ out)
{
    extern __shared__ char smem[];
    float* qT = (float*)(smem + SM_QT);
    float* kT = (float*)(smem + SM_KT);
    float* vT = (float*)(smem + SM_VT);
    const u32 smem_u32 = (u32)__cvta_generic_to_shared(smem);

    const int b    = blockIdx.x;
    const int tid  = threadIdx.x;
    const int warp = tid >> 5;
    const int lane = tid & 31;
    const int g    = lane >> 2;
    const int tig  = lane & 3;

    // ---- prologue: start streaming qkv weight chunks 0 and 1 ----
    {
        #pragma unroll
        for (int st = 0; st < 2; ++st) {
            const uint4* srcH = (const uint4*)(g_wqkvH + st * 3072);
            const uint4* srcL = (const uint4*)(g_wqkvL + st * 3072);
            const u32 dH = smem_u32 + SM_WRING + st * 24576;
            const u32 dL = dH + 12288;
            #pragma unroll
            for (int i = 0; i < 2; ++i) {
                const int idx = tid + i * NTHREADS;
                cp16(dH + idx * 16, srcH + idx);
                cp16(dL + idx * 16, srcL + idx);
            }
            cp_commit();
        }
    }

    // ---- P0: pack x fragments directly from global (bf16 hi/lo) ----
    {
        const float* xb = x + (size_t)b * (N_TOK * CDIM);
        u32* xfH = (u32*)(smem + SM_FRH);
        u32* xfL = (u32*)(smem + SM_FRL);
        for (int s = tid; s < 1024; s += NTHREADS) {
            int k16 = s >> 7, m16 = (s >> 5) & 3, ln = s & 31;
            int gg = ln >> 2, tt = ln & 3;
            int r0 = m16 * 16 + gg, r1 = r0 + 8;
            int c0 = k16 * 16 + 2 * tt;
            float2 p00 = (r0 < N_TOK) ? *(const float2*)&xb[r0 * CDIM + c0]     : make_float2(0.f, 0.f);
            float2 p10 = (r1 < N_TOK) ? *(const float2*)&xb[r1 * CDIM + c0]     : make_float2(0.f, 0.f);
            float2 p01 = (r0 < N_TOK) ? *(const float2*)&xb[r0 * CDIM + c0 + 8] : make_float2(0.f, 0.f);
            float2 p11 = (r1 < N_TOK) ? *(const float2*)&xb[r1 * CDIM + c0 + 8] : make_float2(0.f, 0.f);
            u32 h[4], l[4];
            bsplit(p00.x, p00.y, h[0], l[0]);
            bsplit(p10.x, p10.y, h[1], l[1]);
            bsplit(p01.x, p01.y, h[2], l[2]);
            bsplit(p11.x, p11.y, h[3], l[3]);
            *(uint4*)&xfH[s * 4] = make_uint4(h[0], h[1], h[2], h[3]);
            *(uint4*)&xfL[s * 4] = make_uint4(l[0], l[1], l[2], l[3]);
        }
    }
    __syncthreads();

    // ---- P2: qkv = x @ W. warp = 64 rows x 32 cols (n8 = warp*4+j), smem ring ----
    {
        const u32* xfH = (const u32*)(smem + SM_FRH);
        const u32* xfL = (const u32*)(smem + SM_FRL);

        float c[4][4][4];
        #pragma unroll
        for (int t = 0; t < 4; ++t)
            #pragma unroll
            for (int j = 0; j < 4; ++j)
                #pragma unroll
                for (int q = 0; q < 4; ++q) c[t][j][q] = 0.f;

        #pragma unroll
        for (int k16 = 0; k16 < 8; ++k16) {
            if (k16 < 6) cp_wait<1>(); else cp_wait<0>();
            __syncthreads();

            const int stage = k16 & 1;
            const u32* wch = (const u32*)(smem + SM_WRING + stage * 24576);
            const u32* wcl = wch + 3072;

            u32 bh[4][2], bl[4][2];
            #pragma unroll
            for (int j = 0; j < 4; ++j) {
                const int off = ((warp * 4 + j) * 32 + lane) * 2;
                *(uint2*)bh[j] = *(const uint2*)&wch[off];
                *(uint2*)bl[j] = *(const uint2*)&wcl[off];
            }
            #pragma unroll
            for (int t = 0; t < 4; ++t) {
                u32 aH[4], aL[4];
                uint4 vh = *(const uint4*)&xfH[((k16 * 4 + t) * 32 + lane) * 4];
                uint4 vl = *(const uint4*)&xfL[((k16 * 4 + t) * 32 + lane) * 4];
                aH[0] = vh.x; aH[1] = vh.y; aH[2] = vh.z; aH[3] = vh.w;
                aL[0] = vl.x; aL[1] = vl.y; aL[2] = vl.z; aL[3] = vl.w;
                #pragma unroll
                for (int j = 0; j < 4; ++j) {
                    mma_bf16(c[t][j], aH, bh[j]);
                    mma_bf16(c[t][j], aH, bl[j]);
                    mma_bf16(c[t][j], aL, bh[j]);
                }
            }
            __syncthreads();

            if (k16 < 6) {
                const int nk = k16 + 2;
                const uint4* srcH = (const uint4*)(g_wqkvH + nk * 3072);
                const uint4* srcL = (const uint4*)(g_wqkvL + nk * 3072);
                const u32 dH = smem_u32 + SM_WRING + stage * 24576;
                const u32 dL = dH + 12288;
                #pragma unroll
                for (int i = 0; i < 2; ++i) {
                    const int idx = tid + i * NTHREADS;
                    cp16(dH + idx * 16, srcH + idx);
                    cp16(dL + idx * 16, srcL + idx);
                }
                cp_commit();
            }
        }

        // epilogue: scatter to qT/kT/vT (+bias, q*SCALE); PT=52 -> conflict-free
        float* dstT;
        int cb;
        if (warp < 4)      { dstT = qT; cb = warp * 32; }
        else if (warp < 8) { dstT = kT; cb = (warp - 4) * 32; }
        else               { dstT = vT; cb = (warp - 8) * 32; }
        const bool isq = (warp < 4);
        #pragma unroll
        for (int t = 0; t < 4; ++t) {
            const int r0 = t * 16 + g;
            const int r1 = r0 + 8;
            #pragma unroll
            for (int j = 0; j < 4; ++j) {
                const int col0 = cb + j * 8 + 2 * tig;
                const int gcol = warp * 32 + j * 8 + 2 * tig;
                const float b0 = qkv_b[gcol], b1 = qkv_b[gcol + 1];
                float v00 = c[t][j][0] + b0, v01 = c[t][j][1] + b1;
                float v10 = c[t][j][2] + b0, v11 = c[t][j][3] + b1;
                if (isq) { v00 *= SCALE; v01 *= SCALE; v10 *= SCALE; v11 *= SCALE; }
                if (r0 < 50) { dstT[col0 * PT + r0] = v00; dstT[(col0 + 1) * PT + r0] = v01; }
                if (r1 < 50) { dstT[col0 * PT + r1] = v10; dstT[(col0 + 1) * PT + r1] = v11; }
            }
        }
    }

    // ---- issue proj weight staging (lands during attention) ----
    {
        const uint4* srcH = (const uint4*)g_wprojH;
        const uint4* srcL = (const uint4*)g_wprojL;
        const u32 dH = smem_u32 + SM_PWH;
        const u32 dL = smem_u32 + SM_PWL;
        for (int i = tid; i < 2048; i += NTHREADS) {
            cp16(dH + i * 16, srcH + i);
            cp16(dL + i * 16, srcL + i);
        }
        cp_commit();
    }
    __syncthreads();

    // ---- P3: attention (warps 0-7), vectorized LDS.128 K/V reads ----
    if (tid < 256) {
        const int h  = tid >> 6;
        const int i  = tid & 63;
        const int ii = (i < N_TOK) ? i : (N_TOK - 1);

        u64 sc2[25];
        const u64 z2 = pack2(0.f, 0.f);
        #pragma unroll
        for (int mp = 0; mp < 25; ++mp) sc2[mp] = z2;

        #pragma unroll 4
        for (int d = 0; d < DH; ++d) {
            const int hd = h * DH + d;
            float qd = qT[hd * PT + ii];
            u64 q2 = pack2(qd, qd);
            const ulonglong2* kc = (const ulonglong2*)&kT[hd * PT];
            #pragma unroll
            for (int mq = 0; mq < 12; ++mq) {
                ulonglong2 kk = kc[mq];
                sc2[2 * mq]     = fma2(q2, kk.x, sc2[2 * mq]);
                sc2[2 * mq + 1] = fma2(q2, kk.y, sc2[2 * mq + 1]);
            }
            sc2[24] = fma2(q2, *(const u64*)&kT[hd * PT + 48], sc2[24]);
        }

        float sc[50];
        #pragma unroll
        for (int mp = 0; mp < 25; ++mp) unpack2(sc2[mp], sc[2 * mp], sc[2 * mp + 1]);

        const int w = b & (NWIN - 1);
        const float* ab = &g_abiasT[((w * NH + h) * N_TOK) * 64 + ii];
        #pragma unroll
        for (int m = 0; m < N_TOK; ++m) sc[m] += ab[m * 64];
        sc[49] = -1e30f;

        float mx = sc[0];
        #pragma unroll
        for (int m = 1; m < N_TOK; ++m) mx = fmaxf(mx, sc[m]);
        float sum = 0.f;
        #pragma unroll
        for (int m = 0; m < 50; ++m) {
            float e = __expf(sc[m] - mx);
            sc[m] = e;
            sum += e;
        }
        const float inv = 1.f / sum;
        u64 p2[25];
        #pragma unroll
        for (int mp = 0; mp < 25; ++mp)
            p2[mp] = pack2(sc[2 * mp] * inv, sc[2 * mp + 1] * inv);

        float aov[DH];
        #pragma unroll 4
        for (int d = 0; d < DH; ++d) {
            const int hd = h * DH + d;
            const ulonglong2* vc = (const ulonglong2*)&vT[hd * PT];
            u64 a0 = z2, a1 = z2;
            #pragma unroll
            for (int mq = 0; mq < 12; ++mq) {
                ulonglong2 vv = vc[mq];
                a0 = fma2(p2[2 * mq],     vv.x, a0);
                a1 = fma2(p2[2 * mq + 1], vv.y, a1);
            }
            a0 = fma2(p2[24], *(const u64*)&vT[hd * PT + 48], a0);
            float l0, h0, l1, h1;
            unpack2(a0, l0, h0);
            unpack2(a1, l1, h1);
            aov[d] = (l0 + h0) + (l1 + h1);
        }

        if (i < N_TOK) {
            u32* aoH = (u32*)(smem + SM_FRH);
            u32* aoL = (u32*)(smem + SM_FRL);
            const int mt = i >> 4;
            const int lnbase = (i & 7) * 4;
            const int regm = (i >> 3) & 1;
            #pragma unroll
            for (int d = 0; d < DH; d += 2) {
                const int c0 = h * DH + d;
                const int k16 = c0 >> 4;
                const int ln  = lnbase + ((c0 & 7) >> 1);
                const int reg = regm + 2 * ((c0 >> 3) & 1);
                u32 hi, lo;
                bsplit(aov[d], aov[d + 1], hi, lo);
                const int off = ((k16 * 4 + mt) * 32 + ln) * 4 + reg;
                aoH[off] = hi;
                aoL[off] = lo;
            }
        }
    }
    cp_wait<0>();
    __syncthreads();

    // ---- P4: out = ao @ proj_w + b (warps 0-7), weights from smem ----
    if (tid < 256) {
        const int mw  = warp & 3;
        const int nw2 = warp >> 2;
        const u32* aoH = (const u32*)(smem + SM_FRH);
        const u32* aoL = (const u32*)(smem + SM_FRL);
        const u32* pwH = (const u32*)(smem + SM_PWH);
        const u32* pwL = (const u32*)(smem + SM_PWL);

        float c[8][4];
        #pragma unroll
        for (int j = 0; j < 8; ++j)
            #pragma unroll
            for (int q = 0; q < 4; ++q) c[j][q] = 0.f;

        #pragma unroll
        for (int k16 = 0; k16 < 8; ++k16) {
            u32 aH[4], aL[4];
            uint4 vh = *(const uint4*)&aoH[((k16 * 4 + mw) * 32 + lane) * 4];
            uint4 vl = *(const uint4*)&aoL[((k16 * 4 + mw) * 32 + lane) * 4];
            aH[0] = vh.x; aH[1] = vh.y; aH[2] = vh.z; aH[3] = vh.w;
            aL[0] = vl.x; aL[1] = vl.y; aL[2] = vl.z; aL[3] = vl.w;
            #pragma unroll
            for (int j = 0; j < 8; ++j) {
                const int off = ((k16 * 16 + nw2 * 8 + j) * 32 + lane) * 2;
                u32 bH[2], bL[2];
                *(uint2*)bH = *(const uint2*)&pwH[off];
                *(uint2*)bL = *(const uint2*)&pwL[off];
                mma_bf16(c[j], aH, bH);
                mma_bf16(c[j], aH, bL);
                mma_bf16(c[j], aL, bH);
            }
        }

        float* ob = out + (size_t)b * (N_TOK * CDIM);
        const int r0 = mw * 16 + g;
        const int r1 = r0 + 8;
        #pragma unroll
        for (int j = 0; j < 8; ++j) {
            const int col = nw2 * 64 + j * 8 + 2 * tig;
            const float b0 = proj_b[col], b1 = proj_b[col + 1];
            if (r0 < N_TOK)
                *(float2*)&ob[r0 * CDIM + col] = make_float2(c[j][0] + b0, c[j][1] + b1);
            if (r1 < N_TOK)
                *(float2*)&ob[r1 * CDIM + col] = make_float2(c[j][2] + b0, c[j][3] + b1);
        }
    }
}

extern "C" void kernel_launch(void* const* d_in, const int* in_sizes, int n_in,
                              void* d_out, int out_size)
{
    const float* x          = (const float*)d_in[0];
    const float* mask       = (const float*)d_in[1];
    const float* qkv_w      = (const float*)d_in[2];
    const float* qkv_b      = (const float*)d_in[3];
    const float* proj_w     = (const float*)d_in[4];
    const float* proj_b     = (const float*)d_in[5];
    const float* bias_table = (const float*)d_in[6];
    const int*   rel_index  = (const int*)d_in[7];
    float* out = (float*)d_out;

    const int B = in_sizes[0] / (N_TOK * CDIM);

    {
        const int TOT = NWIN * NH * N_TOK * 64;
        build_abias_kernel<<<(TOT + 255) / 256, 256>>>(mask, bias_table, rel_index);
    }
    {
        u32 *dH, *dL;
        cudaGetSymbolAddress((void**)&dH, g_wqkvH);
        cudaGetSymbolAddress((void**)&dL, g_wqkvL);
        pack_w_kernel<<<(8 * 48 * 32 + 255) / 256, 256>>>(qkv_w, dH, dL, QKV_N, 48, 8 * 48 * 32);
        cudaGetSymbolAddress((void**)&dH, g_wprojH);
        cudaGetSymbolAddress((void**)&dL, g_wprojL);
        pack_w_kernel<<<(8 * 16 * 32 + 255) / 256, 256>>>(proj_w, dH, dL, CDIM, 16, 8 * 16 * 32);
    }

    cudaFuncSetAttribute(win_attn_kernel,
                         cudaFuncAttributeMaxDynamicSharedMemorySize, SMEM_BYTES);
    win_attn_kernel<<<B, NTHREADS, SMEM_BYTES>>>(x, qkv_b, proj_b, out);
}

// round 6
// speedup vs baseline: 2.4221x; 1.1484x over previous
#include <cuda_runtime.h>
#include <cuda_bf16.h>

#define N_TOK    49
#define CDIM     128
#define NH       4
#define DH       32
#define QKV_N    384
#define NWIN     64
#define NTHREADS 384
#define SCALE    0.17677669529663687f

// ---- smem layout (bytes) ----
#define SM_QF_H   0          // Q A-frags / later ao A-frags (overlay), 16KB
#define SM_QF_L   16384
#define SM_KF_H   32768      // K B-frags, 16KB each
#define SM_KF_L   49152
#define SM_VF_H   65536      // V B-frags
#define SM_VF_L   81920
#define SM_OVL    98304      // overlay region
#define SM_XFH    SM_OVL             // x A-frags hi (P0-P2)
#define SM_XFL    (SM_OVL + 16384)
#define SM_WRING  (SM_OVL + 32768)   // qkv weight ring, 2 x 24576
#define SM_PWH    SM_OVL             // proj weights (after P2)
#define SM_PWL    (SM_OVL + 32768)
#define SMEM_BYTES (SM_WRING + 49152)   // 180224

typedef unsigned long long u64;
typedef unsigned int u32;

// ---------------- device globals ----------------
__device__ float g_abias_frag[NWIN * NH * 4 * 8 * 32 * 4];  // [w][h][t][j][lane][q]
__device__ u32 g_wqkvH[8 * 48 * 32 * 2];
__device__ u32 g_wqkvL[8 * 48 * 32 * 2];
__device__ u32 g_wprojH[8 * 16 * 32 * 2];
__device__ u32 g_wprojL[8 * 16 * 32 * 2];

// ---------------- helpers ----------------
__device__ __forceinline__ u64 pack2(float lo, float hi) {
    u64 r; asm("mov.b64 %0, {%1, %2};" : "=l"(r) : "f"(lo), "f"(hi)); return r;
}
__device__ __forceinline__ void unpack2(u64 v, float& lo, float& hi) {
    asm("mov.b64 {%0, %1}, %2;" : "=f"(lo), "=f"(hi) : "l"(v));
}
__device__ __forceinline__ void bsplit(float a, float b, u32& hi, u32& lo) {
    __nv_bfloat16 ah = __float2bfloat16(a), bh = __float2bfloat16(b);
    __nv_bfloat16 al = __float2bfloat16(a - __bfloat162float(ah));
    __nv_bfloat16 bl = __float2bfloat16(b - __bfloat162float(bh));
    hi = (u32)__bfloat16_as_ushort(ah) | ((u32)__bfloat16_as_ushort(bh) << 16);
    lo = (u32)__bfloat16_as_ushort(al) | ((u32)__bfloat16_as_ushort(bl) << 16);
}
__device__ __forceinline__ void mma_bf16(float c[4], const u32 a[4], const u32 b[2]) {
    asm volatile("mma.sync.aligned.m16n8k16.row.col.f32.bf16.bf16.f32 "
                 "{%0,%1,%2,%3}, {%4,%5,%6,%7}, {%8,%9}, {%0,%1,%2,%3};"
                 : "+f"(c[0]), "+f"(c[1]), "+f"(c[2]), "+f"(c[3])
                 : "r"(a[0]), "r"(a[1]), "r"(a[2]), "r"(a[3]), "r"(b[0]), "r"(b[1]));
}
__device__ __forceinline__ void cp16(u32 daddr, const void* src) {
    asm volatile("cp.async.cg.shared.global [%0], [%1], 16;" :: "r"(daddr), "l"(src));
}
__device__ __forceinline__ void cp_commit() { asm volatile("cp.async.commit_group;"); }
template <int N> __device__ __forceinline__ void cp_wait() {
    asm volatile("cp.async.wait_group %0;" :: "n"(N));
}

// ---------------- prep kernels ----------------
__global__ void build_abias_kernel(const float* __restrict__ mask,
                                   const float* __restrict__ bias_table,
                                   const int*   __restrict__ rel_index)
{
    int idx = blockIdx.x * blockDim.x + threadIdx.x;
    const int TOT = NWIN * NH * 4 * 8 * 32 * 4;
    if (idx >= TOT) return;
    int q    = idx & 3;
    int lane = (idx >> 2) & 31;
    int j    = (idx >> 7) & 7;
    int t    = (idx >> 10) & 3;
    int h    = (idx >> 12) & 3;
    int w    = idx >> 14;
    int g = lane >> 2, tig = lane & 3;
    int i = 16 * t + g + 8 * (q >> 1);
    int m = j * 8 + 2 * tig + (q & 1);
    float v;
    if (m >= N_TOK)      v = -1e9f;
    else if (i >= N_TOK) v = 0.f;
    else v = bias_table[rel_index[i * N_TOK + m] * NH + h]
           + mask[(w * N_TOK + i) * N_TOK + m];
    g_abias_frag[idx] = v;
}

__global__ void pack_w_kernel(const float* __restrict__ W, u32* dH, u32* dL,
                              int N, int nn8, int total)
{
    int s = blockIdx.x * blockDim.x + threadIdx.x;
    if (s >= total) return;
    int ln  = s & 31;
    int n8  = (s >> 5) % nn8;
    int k16 = s / (nn8 * 32);
    int gg = ln >> 2, tt = ln & 3;
    int col = n8 * 8 + gg;
    int r = k16 * 16 + 2 * tt;
    float w0 = W[(r + 0) * N + col], w1 = W[(r + 1) * N + col];
    float w2 = W[(r + 8) * N + col], w3 = W[(r + 9) * N + col];
    u32 h0, l0, h1, l1;
    bsplit(w0, w1, h0, l0);
    bsplit(w2, w3, h1, l1);
    dH[s * 2] = h0; dH[s * 2 + 1] = h1;
    dL[s * 2] = l0; dL[s * 2 + 1] = l1;
}

// ---------------- main kernel ----------------
__global__ void __launch_bounds__(NTHREADS, 1)
win_attn_kernel(const float* __restrict__ x,
                const float* __restrict__ qkv_b,
                const float* __restrict__ proj_b,
                float* __restrict__ out)
{
    extern __shared__ char smem[];
    const u32 smem_u32 = (u32)__cvta_generic_to_shared(smem);

    const int b    = blockIdx.x;
    const int tid  = threadIdx.x;
    const int warp = tid >> 5;
    const int lane = tid & 31;
    const int g    = lane >> 2;
    const int tig  = lane & 3;

    // ---- prologue: stream qkv weight chunks 0,1 into the ring ----
    {
        #pragma unroll
        for (int st = 0; st < 2; ++st) {
            const uint4* srcH = (const uint4*)(g_wqkvH + st * 3072);
            const uint4* srcL = (const uint4*)(g_wqkvL + st * 3072);
            const u32 dH = smem_u32 + SM_WRING + st * 24576;
            const u32 dL = dH + 12288;
            #pragma unroll
            for (int i = 0; i < 2; ++i) {
                const int idx = tid + i * NTHREADS;
                cp16(dH + idx * 16, srcH + idx);
                cp16(dL + idx * 16, srcL + idx);
            }
            cp_commit();
        }
    }

    // ---- P0: pack x into A-fragments (bf16 hi/lo), rows >=49 zero ----
    {
        const float* xb = x + (size_t)b * (N_TOK * CDIM);
        u32* xfH = (u32*)(smem + SM_XFH);
        u32* xfL = (u32*)(smem + SM_XFL);
        for (int s = tid; s < 1024; s += NTHREADS) {
            int k16 = s >> 7, m16 = (s >> 5) & 3, ln = s & 31;
            int gg = ln >> 2, tt = ln & 3;
            int r0 = m16 * 16 + gg, r1 = r0 + 8;
            int c0 = k16 * 16 + 2 * tt;
            float2 p00 = (r0 < N_TOK) ? *(const float2*)&xb[r0 * CDIM + c0]     : make_float2(0.f, 0.f);
            float2 p10 = (r1 < N_TOK) ? *(const float2*)&xb[r1 * CDIM + c0]     : make_float2(0.f, 0.f);
            float2 p01 = (r0 < N_TOK) ? *(const float2*)&xb[r0 * CDIM + c0 + 8] : make_float2(0.f, 0.f);
            float2 p11 = (r1 < N_TOK) ? *(const float2*)&xb[r1 * CDIM + c0 + 8] : make_float2(0.f, 0.f);
            u32 h[4], l[4];
            bsplit(p00.x, p00.y, h[0], l[0]);
            bsplit(p10.x, p10.y, h[1], l[1]);
            bsplit(p01.x, p01.y, h[2], l[2]);
            bsplit(p11.x, p11.y, h[3], l[3]);
            *(uint4*)&xfH[s * 4] = make_uint4(h[0], h[1], h[2], h[3]);
            *(uint4*)&xfL[s * 4] = make_uint4(l[0], l[1], l[2], l[3]);
        }
    }
    __syncthreads();

    // ---- P2: qkv GEMM, warp = 64 rows x 32 cols ----
    {
        const u32* xfH = (const u32*)(smem + SM_XFH);
        const u32* xfL = (const u32*)(smem + SM_XFL);

        float c[4][4][4];
        #pragma unroll
        for (int t = 0; t < 4; ++t)
            #pragma unroll
            for (int j = 0; j < 4; ++j)
                #pragma unroll
                for (int q = 0; q < 4; ++q) c[t][j][q] = 0.f;

        #pragma unroll
        for (int k16 = 0; k16 < 8; ++k16) {
            if (k16 < 6) cp_wait<1>(); else cp_wait<0>();
            __syncthreads();

            const int stage = k16 & 1;
            const u32* wch = (const u32*)(smem + SM_WRING + stage * 24576);
            const u32* wcl = wch + 3072;

            u32 bh[4][2], bl[4][2];
            #pragma unroll
            for (int j = 0; j < 4; ++j) {
                const int off = ((warp * 4 + j) * 32 + lane) * 2;
                *(uint2*)bh[j] = *(const uint2*)&wch[off];
                *(uint2*)bl[j] = *(const uint2*)&wcl[off];
            }
            #pragma unroll
            for (int t = 0; t < 4; ++t) {
                u32 aH[4], aL[4];
                uint4 vh = *(const uint4*)&xfH[((k16 * 4 + t) * 32 + lane) * 4];
                uint4 vl = *(const uint4*)&xfL[((k16 * 4 + t) * 32 + lane) * 4];
                aH[0] = vh.x; aH[1] = vh.y; aH[2] = vh.z; aH[3] = vh.w;
                aL[0] = vl.x; aL[1] = vl.y; aL[2] = vl.z; aL[3] = vl.w;
                #pragma unroll
                for (int j = 0; j < 4; ++j) {
                    mma_bf16(c[t][j], aH, bh[j]);
                    mma_bf16(c[t][j], aH, bl[j]);
                    mma_bf16(c[t][j], aL, bh[j]);
                }
            }
            __syncthreads();

            if (k16 < 6) {
                const int nk = k16 + 2;
                const uint4* srcH = (const uint4*)(g_wqkvH + nk * 3072);
                const uint4* srcL = (const uint4*)(g_wqkvL + nk * 3072);
                const u32 dH = smem_u32 + SM_WRING + stage * 24576;
                const u32 dL = dH + 12288;
                #pragma unroll
                for (int i = 0; i < 2; ++i) {
                    const int idx = tid + i * NTHREADS;
                    cp16(dH + idx * 16, srcH + idx);
                    cp16(dL + idx * 16, srcL + idx);
                }
                cp_commit();
            }
        }

        // ---- epilogue: write fragments ----
        float bias0[4], bias1[4];
        #pragma unroll
        for (int j = 0; j < 4; ++j) {
            const int gcol = warp * 32 + j * 8 + 2 * tig;
            bias0[j] = qkv_b[gcol];
            bias1[j] = qkv_b[gcol + 1];
        }

        if (warp < 4) {
            // Q -> A-frag layout (hi/lo), with bias + SCALE
            uint4* qfH = (uint4*)(smem + SM_QF_H);
            uint4* qfL = (uint4*)(smem + SM_QF_L);
            #pragma unroll
            for (int t = 0; t < 4; ++t) {
                #pragma unroll
                for (int jp = 0; jp < 2; ++jp) {
                    const int j0 = 2 * jp, j1 = 2 * jp + 1;
                    float v0 = (c[t][j0][0] + bias0[j0]) * SCALE;
                    float v1 = (c[t][j0][1] + bias1[j0]) * SCALE;
                    float v2 = (c[t][j0][2] + bias0[j0]) * SCALE;
                    float v3 = (c[t][j0][3] + bias1[j0]) * SCALE;
                    float v4 = (c[t][j1][0] + bias0[j1]) * SCALE;
                    float v5 = (c[t][j1][1] + bias1[j1]) * SCALE;
                    float v6 = (c[t][j1][2] + bias0[j1]) * SCALE;
                    float v7 = (c[t][j1][3] + bias1[j1]) * SCALE;
                    u32 h0, l0, h1, l1, h2, l2, h3, l3;
                    bsplit(v0, v1, h0, l0);
                    bsplit(v2, v3, h1, l1);
                    bsplit(v4, v5, h2, l2);
                    bsplit(v6, v7, h3, l3);
                    const int k16 = 2 * warp + jp;
                    const int off = (k16 * 4 + t) * 32 + lane;
                    qfH[off] = make_uint4(h0, h1, h2, h3);
                    qfL[off] = make_uint4(l0, l1, l2, l3);
                }
            }
        } else if (warp < 8) {
            // K -> B-frag layout (same-lane repack)
            const int wk = warp - 4;
            uint2* kfH = (uint2*)(smem + SM_KF_H);
            uint2* kfL = (uint2*)(smem + SM_KF_L);
            #pragma unroll
            for (int t = 0; t < 4; ++t) {
                #pragma unroll
                for (int jp = 0; jp < 2; ++jp) {
                    const int j0 = 2 * jp, j1 = 2 * jp + 1;
                    u32 h00, l00, h01, l01, h10, l10, h11, l11;
                    bsplit(c[t][j0][0] + bias0[j0], c[t][j0][1] + bias1[j0], h00, l00);
                    bsplit(c[t][j1][0] + bias0[j1], c[t][j1][1] + bias1[j1], h01, l01);
                    bsplit(c[t][j0][2] + bias0[j0], c[t][j0][3] + bias1[j0], h10, l10);
                    bsplit(c[t][j1][2] + bias0[j1], c[t][j1][3] + bias1[j1], h11, l11);
                    const int k16 = 2 * wk + jp;
                    kfH[(k16 * 8 + 2 * t) * 32 + lane]     = make_uint2(h00, h01);
                    kfH[(k16 * 8 + 2 * t + 1) * 32 + lane] = make_uint2(h10, h11);
                    kfL[(k16 * 8 + 2 * t) * 32 + lane]     = make_uint2(l00, l01);
                    kfL[(k16 * 8 + 2 * t + 1) * 32 + lane] = make_uint2(l10, l11);
                }
            }
        } else {
            // V -> B-frag layout (key-pair transpose via xor-4 shuffle)
            const int wv = warp - 8;
            uint2* vfH = (uint2*)(smem + SM_VF_H);
            uint2* vfL = (uint2*)(smem + SM_VF_L);
            #pragma unroll
            for (int t = 0; t < 4; ++t) {
                #pragma unroll
                for (int j = 0; j < 4; ++j) {
                    float c0 = c[t][j][0] + bias0[j];
                    float c1 = c[t][j][1] + bias1[j];
                    float c2 = c[t][j][2] + bias0[j];
                    float c3 = c[t][j][3] + bias1[j];
                    u64 p01 = pack2(c0, c1), p23 = pack2(c2, c3);
                    u64 r01 = __shfl_xor_sync(0xffffffffu, p01, 4);
                    u64 r23 = __shfl_xor_sync(0xffffffffu, p23, 4);
                    if (!(g & 1)) {
                        float e0, e1, e2, e3;
                        unpack2(r01, e0, e1);
                        unpack2(r23, e2, e3);
                        u32 h00, l00, h01, l01, h10, l10, h11, l11;
                        bsplit(c0, e0, h00, l00);   // dim d0, reg0 (keys 16t+g, +1)
                        bsplit(c2, e2, h01, l01);   // dim d0, reg1 (keys 16t+8+g, +1)
                        bsplit(c1, e1, h10, l10);   // dim d1, reg0
                        bsplit(c3, e3, h11, l11);   // dim d1, reg1
                        const int n8 = wv * 4 + j;
                        const int kp = g >> 1;
                        const int base = (t * 16 + n8) * 32;
                        vfH[base + (2 * tig) * 4 + kp]     = make_uint2(h00, h01);
                        vfH[base + (2 * tig + 1) * 4 + kp] = make_uint2(h10, h11);
                        vfL[base + (2 * tig) * 4 + kp]     = make_uint2(l00, l01);
                        vfL[base + (2 * tig + 1) * 4 + kp] = make_uint2(l10, l11);
                    }
                }
            }
        }
    }

    // ---- stage proj weights (lands during attention) ----
    {
        const uint4* srcH = (const uint4*)g_wprojH;
        const uint4* srcL = (const uint4*)g_wprojL;
        const u32 dH = smem_u32 + SM_PWH;
        const u32 dL = smem_u32 + SM_PWL;
        for (int i = tid; i < 2048; i += NTHREADS) {
            cp16(dH + i * 16, srcH + i);
            cp16(dL + i * 16, srcL + i);
        }
        cp_commit();
    }
    __syncthreads();

    // ---- P3: attention on tensor cores (warps 0-7: warp = (head, row-half)) ----
    if (warp < 8) {
        const int h  = warp >> 1;
        const int mh = warp & 1;

        // Q A-frags
        u32 qh[2][2][4], ql[2][2][4];
        {
            const uint4* qfH = (const uint4*)(smem + SM_QF_H);
            const uint4* qfL = (const uint4*)(smem + SM_QF_L);
            #pragma unroll
            for (int tp = 0; tp < 2; ++tp)
                #pragma unroll
                for (int kk = 0; kk < 2; ++kk) {
                    const int off = ((2 * h + kk) * 4 + 2 * mh + tp) * 32 + lane;
                    uint4 vh = qfH[off], vl = qfL[off];
                    qh[tp][kk][0] = vh.x; qh[tp][kk][1] = vh.y; qh[tp][kk][2] = vh.z; qh[tp][kk][3] = vh.w;
                    ql[tp][kk][0] = vl.x; ql[tp][kk][1] = vl.y; ql[tp][kk][2] = vl.z; ql[tp][kk][3] = vl.w;
                }
        }

        // scores
        float s[2][8][4];
        #pragma unroll
        for (int tp = 0; tp < 2; ++tp)
            #pragma unroll
            for (int j = 0; j < 8; ++j)
                #pragma unroll
                for (int q = 0; q < 4; ++q) s[tp][j][q] = 0.f;
        {
            const uint2* kfH = (const uint2*)(smem + SM_KF_H);
            const uint2* kfL = (const uint2*)(smem + SM_KF_L);
            #pragma unroll
            for (int kk = 0; kk < 2; ++kk) {
                #pragma unroll
                for (int j = 0; j < 8; ++j) {
                    uint2 bh2 = kfH[((2 * h + kk) * 8 + j) * 32 + lane];
                    uint2 bl2 = kfL[((2 * h + kk) * 8 + j) * 32 + lane];
                    u32 bH[2] = {bh2.x, bh2.y};
                    u32 bL[2] = {bl2.x, bl2.y};
                    #pragma unroll
                    for (int tp = 0; tp < 2; ++tp) {
                        mma_bf16(s[tp][j], qh[tp][kk], bH);
                        mma_bf16(s[tp][j], qh[tp][kk], bL);
                        mma_bf16(s[tp][j], ql[tp][kk], bH);
                    }
                }
            }
        }

        // bias + mask (fragment-ordered table)
        {
            const int w = b & (NWIN - 1);
            const float4* ab = (const float4*)(g_abias_frag + (size_t)(w * NH + h) * 4096);
            #pragma unroll
            for (int tp = 0; tp < 2; ++tp) {
                const int t = 2 * mh + tp;
                #pragma unroll
                for (int j = 0; j < 8; ++j) {
                    float4 bb = ab[(t * 8 + j) * 32 + lane];
                    s[tp][j][0] += bb.x; s[tp][j][1] += bb.y;
                    s[tp][j][2] += bb.z; s[tp][j][3] += bb.w;
                }
            }
        }

        // softmax (rows: (tp, q>>1); reduce over j,q&1 then tig quad)
        float inv[2][2];
        #pragma unroll
        for (int tp = 0; tp < 2; ++tp) {
            #pragma unroll
            for (int rh = 0; rh < 2; ++rh) {
                float mx = -1e30f;
                #pragma unroll
                for (int j = 0; j < 8; ++j) {
                    mx = fmaxf(mx, s[tp][j][2 * rh]);
                    mx = fmaxf(mx, s[tp][j][2 * rh + 1]);
                }
                mx = fmaxf(mx, __shfl_xor_sync(0xffffffffu, mx, 1));
                mx = fmaxf(mx, __shfl_xor_sync(0xffffffffu, mx, 2));
                float sum = 0.f;
                #pragma unroll
                for (int j = 0; j < 8; ++j) {
                    float e0 = __expf(s[tp][j][2 * rh] - mx);
                    float e1 = __expf(s[tp][j][2 * rh + 1] - mx);
                    s[tp][j][2 * rh] = e0;
                    s[tp][j][2 * rh + 1] = e1;
                    sum += e0 + e1;
                }
                sum += __shfl_xor_sync(0xffffffffu, sum, 1);
                sum += __shfl_xor_sync(0xffffffffu, sum, 2);
                inv[tp][rh] = 1.f / sum;
            }
        }

        // pack P into A-frags (in-register C->A conversion), hi/lo
        u32 ph[2][4][4], pl[2][4][4];
        #pragma unroll
        for (int tp = 0; tp < 2; ++tp) {
            #pragma unroll
            for (int kk = 0; kk < 4; ++kk) {
                bsplit(s[tp][2 * kk][0] * inv[tp][0], s[tp][2 * kk][1] * inv[tp][0],
                       ph[tp][kk][0], pl[tp][kk][0]);
                bsplit(s[tp][2 * kk][2] * inv[tp][1], s[tp][2 * kk][3] * inv[tp][1],
                       ph[tp][kk][1], pl[tp][kk][1]);
                bsplit(s[tp][2 * kk + 1][0] * inv[tp][0], s[tp][2 * kk + 1][1] * inv[tp][0],
                       ph[tp][kk][2], pl[tp][kk][2]);
                bsplit(s[tp][2 * kk + 1][2] * inv[tp][1], s[tp][2 * kk + 1][3] * inv[tp][1],
                       ph[tp][kk][3], pl[tp][kk][3]);
            }
        }

        // PV
        float o[2][4][4];
        #pragma unroll
        for (int tp = 0; tp < 2; ++tp)
            #pragma unroll
            for (int jd = 0; jd < 4; ++jd)
                #pragma unroll
                for (int q = 0; q < 4; ++q) o[tp][jd][q] = 0.f;
        {
            const uint2* vfH = (const uint2*)(smem + SM_VF_H);
            const uint2* vfL = (const uint2*)(smem + SM_VF_L);
            #pragma unroll
            for (int kk = 0; kk < 4; ++kk) {
                #pragma unroll
                for (int jd = 0; jd < 4; ++jd) {
                    uint2 bh2 = vfH[(kk * 16 + 4 * h + jd) * 32 + lane];
                    uint2 bl2 = vfL[(kk * 16 + 4 * h + jd) * 32 + lane];
                    u32 bH[2] = {bh2.x, bh2.y};
                    u32 bL[2] = {bl2.x, bl2.y};
                    #pragma unroll
                    for (int tp = 0; tp < 2; ++tp) {
                        mma_bf16(o[tp][jd], ph[tp][kk], bH);
                        mma_bf16(o[tp][jd], ph[tp][kk], bL);
                        mma_bf16(o[tp][jd], pl[tp][kk], bH);
                    }
                }
            }
        }

        // ao -> A-frags for proj (overlay on Q frag region; warp writes its own slots)
        {
            uint4* aoH = (uint4*)(smem + SM_QF_H);
            uint4* aoL = (uint4*)(smem + SM_QF_L);
            #pragma unroll
            for (int tp = 0; tp < 2; ++tp) {
                #pragma unroll
                for (int kd = 0; kd < 2; ++kd) {
                    u32 h0, l0, h1, l1, h2, l2, h3, l3;
                    bsplit(o[tp][2 * kd][0], o[tp][2 * kd][1], h0, l0);
                    bsplit(o[tp][2 * kd][2], o[tp][2 * kd][3], h1, l1);
                    bsplit(o[tp][2 * kd + 1][0], o[tp][2 * kd + 1][1], h2, l2);
                    bsplit(o[tp][2 * kd + 1][2], o[tp][2 * kd + 1][3], h3, l3);
                    const int off = ((2 * h + kd) * 4 + 2 * mh + tp) * 32 + lane;
                    aoH[off] = make_uint4(h0, h1, h2, h3);
                    aoL[off] = make_uint4(l0, l1, l2, l3);
                }
            }
        }
    }
    cp_wait<0>();
    __syncthreads();

    // ---- P4: proj (warps 0-7), weights from smem ----
    if (warp < 8) {
        const int mw  = warp & 3;
        const int nw2 = warp >> 2;
        const u32* aoH = (const u32*)(smem + SM_QF_H);
        const u32* aoL = (const u32*)(smem + SM_QF_L);
        const u32* pwH = (const u32*)(smem + SM_PWH);
        const u32* pwL = (const u32*)(smem + SM_PWL);

        float c[8][4];
        #pragma unroll
        for (int j = 0; j < 8; ++j)
            #pragma unroll
            for (int q = 0; q < 4; ++q) c[j][q] = 0.f;

        #pragma unroll
        for (int k16 = 0; k16 < 8; ++k16) {
            u32 aH[4], aL[4];
            uint4 vh = *(const uint4*)&aoH[((k16 * 4 + mw) * 32 + lane) * 4];
            uint4 vl = *(const uint4*)&aoL[((k16 * 4 + mw) * 32 + lane) * 4];
            aH[0] = vh.x; aH[1] = vh.y; aH[2] = vh.z; aH[3] = vh.w;
            aL[0] = vl.x; aL[1] = vl.y; aL[2] = vl.z; aL[3] = vl.w;
            #pragma unroll
            for (int j = 0; j < 8; ++j) {
                const int off = ((k16 * 16 + nw2 * 8 + j) * 32 + lane) * 2;
                u32 bH[2], bL[2];
                *(uint2*)bH = *(const uint2*)&pwH[off];
                *(uint2*)bL = *(const uint2*)&pwL[off];
                mma_bf16(c[j], aH, bH);
                mma_bf16(c[j], aH, bL);
                mma_bf16(c[j], aL, bH);
            }
        }

        float* ob = out + (size_t)b * (N_TOK * CDIM);
        const int r0 = mw * 16 + g;
        const int r1 = r0 + 8;
        #pragma unroll
        for (int j = 0; j < 8; ++j) {
            const int col = nw2 * 64 + j * 8 + 2 * tig;
            const float b0 = proj_b[col], b1 = proj_b[col + 1];
            if (r0 < N_TOK)
                *(float2*)&ob[r0 * CDIM + col] = make_float2(c[j][0] + b0, c[j][1] + b1);
            if (r1 < N_TOK)
                *(float2*)&ob[r1 * CDIM + col] = make_float2(c[j][2] + b0, c[j][3] + b1);
        }
    }
}

extern "C" void kernel_launch(void* const* d_in, const int* in_sizes, int n_in,
                              void* d_out, int out_size)
{
    const float* x          = (const float*)d_in[0];
    const float* mask       = (const float*)d_in[1];
    const float* qkv_w      = (const float*)d_in[2];
    const float* qkv_b      = (const float*)d_in[3];
    const float* proj_w     = (const float*)d_in[4];
    const float* proj_b     = (const float*)d_in[5];
    const float* bias_table = (const float*)d_in[6];
    const int*   rel_index  = (const int*)d_in[7];
    float* out = (float*)d_out;

    const int B = in_sizes[0] / (N_TOK * CDIM);

    {
        const int TOT = NWIN * NH * 4 * 8 * 32 * 4;
        build_abias_kernel<<<(TOT + 255) / 256, 256>>>(mask, bias_table, rel_index);
    }
    {
        u32 *dH, *dL;
        cudaGetSymbolAddress((void**)&dH, g_wqkvH);
        cudaGetSymbolAddress((void**)&dL, g_wqkvL);
        pack_w_kernel<<<(8 * 48 * 32 + 255) / 256, 256>>>(qkv_w, dH, dL, QKV_N, 48, 8 * 48 * 32);
        cudaGetSymbolAddress((void**)&dH, g_wprojH);
        cudaGetSymbolAddress((void**)&dL, g_wprojL);
        pack_w_kernel<<<(8 * 16 * 32 + 255) / 256, 256>>>(proj_w, dH, dL, CDIM, 16, 8 * 16 * 32);
    }

    cudaFuncSetAttribute(win_attn_kernel,
                         cudaFuncAttributeMaxDynamicSharedMemorySize, SMEM_BYTES);
    win_attn_kernel<<<B, NTHREADS, SMEM_BYTES>>>(x, qkv_b, proj_b, out);
}

// round 7
// speedup vs baseline: 2.6222x; 1.0826x over previous
#include <cuda_runtime.h>
#include <cuda_bf16.h>

#define N_TOK    49
#define CDIM     128
#define NH       4
#define DH       32
#define QKV_N    384
#define NWIN     64
#define NTHREADS 512
#define SCALE    0.17677669529663687f

// ---- smem layout (bytes) ----
#define SM_QF_H   0          // Q A-frags / later ao A-frags (overlay)
#define SM_QF_L   16384
#define SM_KF_H   32768
#define SM_KF_L   49152
#define SM_VF_H   65536
#define SM_VF_L   81920
#define SM_XFH    98304      // x A-frags (P0-P2); PW_H overlays after P2
#define SM_XFL    114688
#define SM_RING   131072     // 4 slots x 24576
#define SM_PWH    98304      // proj weights hi (overlay xf)
#define SM_PWL    131072     // proj weights lo (overlay ring slots 0-1)
#define SMEM_BYTES 229376

typedef unsigned long long u64;
typedef unsigned int u32;

// ---------------- device globals ----------------
__device__ float g_abias_frag[NWIN * NH * 4 * 8 * 32 * 4];  // [w][h][t][j][lane][q]
__device__ u32 g_wqkvH[8 * 48 * 32 * 2];   // [k16][n8][lane][2]
__device__ u32 g_wqkvL[8 * 48 * 32 * 2];
__device__ u32 g_wprojH[8 * 16 * 32 * 2];
__device__ u32 g_wprojL[8 * 16 * 32 * 2];

// ---------------- helpers ----------------
__device__ __forceinline__ u64 pack2(float lo, float hi) {
    u64 r; asm("mov.b64 %0, {%1, %2};" : "=l"(r) : "f"(lo), "f"(hi)); return r;
}
__device__ __forceinline__ void unpack2(u64 v, float& lo, float& hi) {
    asm("mov.b64 {%0, %1}, %2;" : "=f"(lo), "=f"(hi) : "l"(v));
}
__device__ __forceinline__ void bsplit(float a, float b, u32& hi, u32& lo) {
    __nv_bfloat16 ah = __float2bfloat16(a), bh = __float2bfloat16(b);
    __nv_bfloat16 al = __float2bfloat16(a - __bfloat162float(ah));
    __nv_bfloat16 bl = __float2bfloat16(b - __bfloat162float(bh));
    hi = (u32)__bfloat16_as_ushort(ah) | ((u32)__bfloat16_as_ushort(bh) << 16);
    lo = (u32)__bfloat16_as_ushort(al) | ((u32)__bfloat16_as_ushort(bl) << 16);
}
__device__ __forceinline__ void mma_bf16(float c[4], const u32 a[4], const u32 b[2]) {
    asm volatile("mma.sync.aligned.m16n8k16.row.col.f32.bf16.bf16.f32 "
                 "{%0,%1,%2,%3}, {%4,%5,%6,%7}, {%8,%9}, {%0,%1,%2,%3};"
                 : "+f"(c[0]), "+f"(c[1]), "+f"(c[2]), "+f"(c[3])
                 : "r"(a[0]), "r"(a[1]), "r"(a[2]), "r"(a[3]), "r"(b[0]), "r"(b[1]));
}
__device__ __forceinline__ void cp16(u32 daddr, const void* src) {
    asm volatile("cp.async.cg.shared.global [%0], [%1], 16;" :: "r"(daddr), "l"(src));
}
__device__ __forceinline__ void cp_commit() { asm volatile("cp.async.commit_group;"); }
template <int N> __device__ __forceinline__ void cp_wait() {
    asm volatile("cp.async.wait_group %0;" :: "n"(N));
}

// ---------------- prep kernels ----------------
__global__ void build_abias_kernel(const float* __restrict__ mask,
                                   const float* __restrict__ bias_table,
                                   const int*   __restrict__ rel_index)
{
    int idx = blockIdx.x * blockDim.x + threadIdx.x;
    const int TOT = NWIN * NH * 4 * 8 * 32 * 4;
    if (idx >= TOT) return;
    int q    = idx & 3;
    int lane = (idx >> 2) & 31;
    int j    = (idx >> 7) & 7;
    int t    = (idx >> 10) & 3;
    int h    = (idx >> 12) & 3;
    int w    = idx >> 14;
    int g = lane >> 2, tig = lane & 3;
    int i = 16 * t + g + 8 * (q >> 1);
    int m = j * 8 + 2 * tig + (q & 1);
    float v;
    if (m >= N_TOK)      v = -1e9f;
    else if (i >= N_TOK) v = 0.f;
    else v = bias_table[rel_index[i * N_TOK + m] * NH + h]
           + mask[(w * N_TOK + i) * N_TOK + m];
    g_abias_frag[idx] = v;
}

__global__ void pack_w_kernel(const float* __restrict__ W, u32* dH, u32* dL,
                              int N, int nn8, int total)
{
    int s = blockIdx.x * blockDim.x + threadIdx.x;
    if (s >= total) return;
    int ln  = s & 31;
    int n8  = (s >> 5) % nn8;
    int k16 = s / (nn8 * 32);
    int gg = ln >> 2, tt = ln & 3;
    int col = n8 * 8 + gg;
    int r = k16 * 16 + 2 * tt;
    float w0 = W[(r + 0) * N + col], w1 = W[(r + 1) * N + col];
    float w2 = W[(r + 8) * N + col], w3 = W[(r + 9) * N + col];
    u32 h0, l0, h1, l1;
    bsplit(w0, w1, h0, l0);
    bsplit(w2, w3, h1, l1);
    dH[s * 2] = h0; dH[s * 2 + 1] = h1;
    dL[s * 2] = l0; dL[s * 2 + 1] = l1;
}

// ---------------- main kernel ----------------
__global__ void __launch_bounds__(NTHREADS, 1)
win_attn_kernel(const float* __restrict__ x,
                const float* __restrict__ qkv_b,
                const float* __restrict__ proj_b,
                float* __restrict__ out)
{
    extern __shared__ char smem[];
    const u32 smem_u32 = (u32)__cvta_generic_to_shared(smem);

    const int b    = blockIdx.x;
    const int tid  = threadIdx.x;
    const int warp = tid >> 5;
    const int lane = tid & 31;
    const int g    = lane >> 2;
    const int tig  = lane & 3;

    // ---- prologue: stream qkv weight k16 slots 0..3 (4 commit groups) ----
    {
        #pragma unroll
        for (int st = 0; st < 4; ++st) {
            const uint4* srcH = (const uint4*)(g_wqkvH + st * 3072);
            const uint4* srcL = (const uint4*)(g_wqkvL + st * 3072);
            const u32 dH = smem_u32 + SM_RING + st * 24576;
            const u32 dL = dH + 12288;
            {
                const int idx = tid;   // 512 threads, 768 uint4 H + 768 L per slot
                cp16(dH + idx * 16, srcH + idx);
                cp16(dL + idx * 16, srcL + idx);
                if (idx < 256) {
                    cp16(dH + (idx + 512) * 16, srcH + idx + 512);
                    cp16(dL + (idx + 512) * 16, srcL + idx + 512);
                }
            }
            cp_commit();
        }
    }

    // ---- P0: pack x into A-fragments (bf16 hi/lo), rows >=49 zero ----
    {
        const float* xb = x + (size_t)b * (N_TOK * CDIM);
        u32* xfH = (u32*)(smem + SM_XFH);
        u32* xfL = (u32*)(smem + SM_XFL);
        #pragma unroll
        for (int it = 0; it < 2; ++it) {
            int s = tid + it * NTHREADS;
            int k16 = s >> 7, m16 = (s >> 5) & 3, ln = s & 31;
            int gg = ln >> 2, tt = ln & 3;
            int r0 = m16 * 16 + gg, r1 = r0 + 8;
            int c0 = k16 * 16 + 2 * tt;
            float2 p00 = (r0 < N_TOK) ? *(const float2*)&xb[r0 * CDIM + c0]     : make_float2(0.f, 0.f);
            float2 p10 = (r1 < N_TOK) ? *(const float2*)&xb[r1 * CDIM + c0]     : make_float2(0.f, 0.f);
            float2 p01 = (r0 < N_TOK) ? *(const float2*)&xb[r0 * CDIM + c0 + 8] : make_float2(0.f, 0.f);
            float2 p11 = (r1 < N_TOK) ? *(const float2*)&xb[r1 * CDIM + c0 + 8] : make_float2(0.f, 0.f);
            u32 h[4], l[4];
            bsplit(p00.x, p00.y, h[0], l[0]);
            bsplit(p10.x, p10.y, h[1], l[1]);
            bsplit(p01.x, p01.y, h[2], l[2]);
            bsplit(p11.x, p11.y, h[3], l[3]);
            *(uint4*)&xfH[s * 4] = make_uint4(h[0], h[1], h[2], h[3]);
            *(uint4*)&xfL[s * 4] = make_uint4(l[0], l[1], l[2], l[3]);
        }
    }
    __syncthreads();

    // ---- P2: qkv GEMM, 16 warps, warp tile = 32 rows x 48 cols ----
    {
        const int mw = warp & 1;          // rows mw*32..+31 (t = 2mw, 2mw+1)
        const int nw = warp >> 1;         // cols nw*48..+47 (n8 = nw*6+j)
        const u32* xfH = (const u32*)(smem + SM_XFH);
        const u32* xfL = (const u32*)(smem + SM_XFL);

        float c[2][6][4];
        #pragma unroll
        for (int tp = 0; tp < 2; ++tp)
            #pragma unroll
            for (int j = 0; j < 6; ++j)
                #pragma unroll
                for (int q = 0; q < 4; ++q) c[tp][j][q] = 0.f;

        #pragma unroll
        for (int kp = 0; kp < 4; ++kp) {
            if (kp == 0)      cp_wait<2>();
            else if (kp == 3) cp_wait<0>();
            else              cp_wait<1>();
            __syncthreads();

            #pragma unroll
            for (int kh = 0; kh < 2; ++kh) {
                const int k16 = 2 * kp + kh;
                const int slot = k16 & 3;
                const u32* wch = (const u32*)(smem + SM_RING + slot * 24576);
                const u32* wcl = wch + 3072;

                u32 bh[6][2], bl[6][2];
                #pragma unroll
                for (int j = 0; j < 6; ++j) {
                    const int off = ((nw * 6 + j) * 32 + lane) * 2;
                    *(uint2*)bh[j] = *(const uint2*)&wch[off];
                    *(uint2*)bl[j] = *(const uint2*)&wcl[off];
                }
                #pragma unroll
                for (int tp = 0; tp < 2; ++tp) {
                    const int t = 2 * mw + tp;
                    u32 aH[4], aL[4];
                    uint4 vh = *(const uint4*)&xfH[((k16 * 4 + t) * 32 + lane) * 4];
                    uint4 vl = *(const uint4*)&xfL[((k16 * 4 + t) * 32 + lane) * 4];
                    aH[0] = vh.x; aH[1] = vh.y; aH[2] = vh.z; aH[3] = vh.w;
                    aL[0] = vl.x; aL[1] = vl.y; aL[2] = vl.z; aL[3] = vl.w;
                    #pragma unroll
                    for (int j = 0; j < 6; ++j) {
                        mma_bf16(c[tp][j], aH, bh[j]);
                        mma_bf16(c[tp][j], aH, bl[j]);
                        mma_bf16(c[tp][j], aL, bh[j]);
                    }
                }
            }
            __syncthreads();

            if (kp < 2) {
                #pragma unroll
                for (int kh = 0; kh < 2; ++kh) {
                    const int nk = 4 + 2 * kp + kh;
                    const int slot = nk & 3;
                    const uint4* srcH = (const uint4*)(g_wqkvH + nk * 3072);
                    const uint4* srcL = (const uint4*)(g_wqkvL + nk * 3072);
                    const u32 dH = smem_u32 + SM_RING + slot * 24576;
                    const u32 dL = dH + 12288;
                    cp16(dH + tid * 16, srcH + tid);
                    cp16(dL + tid * 16, srcL + tid);
                    if (tid < 256) {
                        cp16(dH + (tid + 512) * 16, srcH + tid + 512);
                        cp16(dL + (tid + 512) * 16, srcL + tid + 512);
                    }
                }
                cp_commit();
            }
        }

        // ---- epilogue: per-k16 region dispatch (Q A-frag / K B-frag / V B-frag) ----
        float bias0[6], bias1[6];
        #pragma unroll
        for (int j = 0; j < 6; ++j) {
            const int gcol = nw * 48 + j * 8 + 2 * tig;
            bias0[j] = qkv_b[gcol];
            bias1[j] = qkv_b[gcol + 1];
        }

        #pragma unroll
        for (int lk = 0; lk < 3; ++lk) {
            const int gk16 = nw * 3 + lk;     // global col-k16, 0..23
            const int j0 = 2 * lk, j1 = 2 * lk + 1;
            if (gk16 < 8) {
                // ---- Q: A-frag layout, +bias, *SCALE ----
                uint4* qfH = (uint4*)(smem + SM_QF_H);
                uint4* qfL = (uint4*)(smem + SM_QF_L);
                #pragma unroll
                for (int tp = 0; tp < 2; ++tp) {
                    const int t = 2 * mw + tp;
                    float v0 = (c[tp][j0][0] + bias0[j0]) * SCALE;
                    float v1 = (c[tp][j0][1] + bias1[j0]) * SCALE;
                    float v2 = (c[tp][j0][2] + bias0[j0]) * SCALE;
                    float v3 = (c[tp][j0][3] + bias1[j0]) * SCALE;
                    float v4 = (c[tp][j1][0] + bias0[j1]) * SCALE;
                    float v5 = (c[tp][j1][1] + bias1[j1]) * SCALE;
                    float v6 = (c[tp][j1][2] + bias0[j1]) * SCALE;
                    float v7 = (c[tp][j1][3] + bias1[j1]) * SCALE;
                    u32 h0, l0, h1, l1, h2, l2, h3, l3;
                    bsplit(v0, v1, h0, l0);
                    bsplit(v2, v3, h1, l1);
                    bsplit(v4, v5, h2, l2);
                    bsplit(v6, v7, h3, l3);
                    const int off = (gk16 * 4 + t) * 32 + lane;
                    qfH[off] = make_uint4(h0, h1, h2, h3);
                    qfL[off] = make_uint4(l0, l1, l2, l3);
                }
            } else if (gk16 < 16) {
                // ---- K: B-frag layout (same-lane repack) ----
                const int kk16 = gk16 - 8;
                uint2* kfH = (uint2*)(smem + SM_KF_H);
                uint2* kfL = (uint2*)(smem + SM_KF_L);
                #pragma unroll
                for (int tp = 0; tp < 2; ++tp) {
                    const int t = 2 * mw + tp;
                    u32 h00, l00, h01, l01, h10, l10, h11, l11;
                    bsplit(c[tp][j0][0] + bias0[j0], c[tp][j0][1] + bias1[j0], h00, l00);
                    bsplit(c[tp][j1][0] + bias0[j1], c[tp][j1][1] + bias1[j1], h01, l01);
                    bsplit(c[tp][j0][2] + bias0[j0], c[tp][j0][3] + bias1[j0], h10, l10);
                    bsplit(c[tp][j1][2] + bias0[j1], c[tp][j1][3] + bias1[j1], h11, l11);
                    kfH[(kk16 * 8 + 2 * t) * 32 + lane]     = make_uint2(h00, h01);
                    kfH[(kk16 * 8 + 2 * t + 1) * 32 + lane] = make_uint2(h10, h11);
                    kfL[(kk16 * 8 + 2 * t) * 32 + lane]     = make_uint2(l00, l01);
                    kfL[(kk16 * 8 + 2 * t + 1) * 32 + lane] = make_uint2(l10, l11);
                }
            } else {
                // ---- V: B-frag layout (key-pair transpose via xor-4 shuffle) ----
                uint2* vfH = (uint2*)(smem + SM_VF_H);
                uint2* vfL = (uint2*)(smem + SM_VF_L);
                #pragma unroll
                for (int jj = 0; jj < 2; ++jj) {
                    const int j = 2 * lk + jj;
                    const int n8v = (gk16 - 16) * 2 + jj;  // 0..15
                    #pragma unroll
                    for (int tp = 0; tp < 2; ++tp) {
                        const int t = 2 * mw + tp;
                        float c0 = c[tp][j][0] + bias0[j];
                        float c1 = c[tp][j][1] + bias1[j];
                        float c2 = c[tp][j][2] + bias0[j];
                        float c3 = c[tp][j][3] + bias1[j];
                        u64 p01 = pack2(c0, c1), p23 = pack2(c2, c3);
                        u64 r01 = __shfl_xor_sync(0xffffffffu, p01, 4);
                        u64 r23 = __shfl_xor_sync(0xffffffffu, p23, 4);
                        if (!(g & 1)) {
                            float e0, e1, e2, e3;
                            unpack2(r01, e0, e1);
                            unpack2(r23, e2, e3);
                            u32 h00, l00, h01, l01, h10, l10, h11, l11;
                            bsplit(c0, e0, h00, l00);
                            bsplit(c2, e2, h01, l01);
                            bsplit(c1, e1, h10, l10);
                            bsplit(c3, e3, h11, l11);
                            const int kp2 = g >> 1;
                            const int base = (t * 16 + n8v) * 32;
                            vfH[base + (2 * tig) * 4 + kp2]     = make_uint2(h00, h01);
                            vfH[base + (2 * tig + 1) * 4 + kp2] = make_uint2(h10, h11);
                            vfL[base + (2 * tig) * 4 + kp2]     = make_uint2(l00, l01);
                            vfL[base + (2 * tig + 1) * 4 + kp2] = make_uint2(l10, l11);
                        }
                    }
                }
            }
        }
    }

    // ---- stage proj weights (lands during attention) ----
    {
        const uint4* srcH = (const uint4*)g_wprojH;
        const uint4* srcL = (const uint4*)g_wprojL;
        const u32 dH = smem_u32 + SM_PWH;
        const u32 dL = smem_u32 + SM_PWL;
        #pragma unroll
        for (int i = 0; i < 4; ++i) {
            const int idx = tid + i * NTHREADS;
            cp16(dH + idx * 16, srcH + idx);
            cp16(dL + idx * 16, srcL + idx);
        }
        cp_commit();
    }
    __syncthreads();

    // ---- P3: attention on tensor cores, 16 warps: warp = (head h, m16 tile t) ----
    {
        const int h = warp >> 2;
        const int t = warp & 3;

        // Q A-frags
        u32 qh[2][4], ql[2][4];
        {
            const uint4* qfH = (const uint4*)(smem + SM_QF_H);
            const uint4* qfL = (const uint4*)(smem + SM_QF_L);
            #pragma unroll
            for (int kk = 0; kk < 2; ++kk) {
                const int off = ((2 * h + kk) * 4 + t) * 32 + lane;
                uint4 vh = qfH[off], vl = qfL[off];
                qh[kk][0] = vh.x; qh[kk][1] = vh.y; qh[kk][2] = vh.z; qh[kk][3] = vh.w;
                ql[kk][0] = vl.x; ql[kk][1] = vl.y; ql[kk][2] = vl.z; ql[kk][3] = vl.w;
            }
        }

        // scores
        float s[8][4];
        #pragma unroll
        for (int j = 0; j < 8; ++j)
            #pragma unroll
            for (int q = 0; q < 4; ++q) s[j][q] = 0.f;
        {
            const uint2* kfH = (const uint2*)(smem + SM_KF_H);
            const uint2* kfL = (const uint2*)(smem + SM_KF_L);
            #pragma unroll
            for (int kk = 0; kk < 2; ++kk) {
                #pragma unroll
                for (int j = 0; j < 8; ++j) {
                    uint2 bh2 = kfH[((2 * h + kk) * 8 + j) * 32 + lane];
                    uint2 bl2 = kfL[((2 * h + kk) * 8 + j) * 32 + lane];
                    u32 bH[2] = {bh2.x, bh2.y};
                    u32 bL[2] = {bl2.x, bl2.y};
                    mma_bf16(s[j], qh[kk], bH);
                    mma_bf16(s[j], qh[kk], bL);
                    mma_bf16(s[j], ql[kk], bH);
                }
            }
        }

        // bias + mask (fragment-ordered)
        {
            const int w = b & (NWIN - 1);
            const float4* ab = (const float4*)(g_abias_frag + (size_t)(w * NH + h) * 4096);
            #pragma unroll
            for (int j = 0; j < 8; ++j) {
                float4 bb = ab[(t * 8 + j) * 32 + lane];
                s[j][0] += bb.x; s[j][1] += bb.y;
                s[j][2] += bb.z; s[j][3] += bb.w;
            }
        }

        // softmax (rows g and g+8; reduce over j,q-pair then tig quad)
        float inv[2];
        #pragma unroll
        for (int rh = 0; rh < 2; ++rh) {
            float mx = -1e30f;
            #pragma unroll
            for (int j = 0; j < 8; ++j) {
                mx = fmaxf(mx, s[j][2 * rh]);
                mx = fmaxf(mx, s[j][2 * rh + 1]);
            }
            mx = fmaxf(mx, __shfl_xor_sync(0xffffffffu, mx, 1));
            mx = fmaxf(mx, __shfl_xor_sync(0xffffffffu, mx, 2));
            float sum = 0.f;
            #pragma unroll
            for (int j = 0; j < 8; ++j) {
                float e0 = __expf(s[j][2 * rh] - mx);
                float e1 = __expf(s[j][2 * rh + 1] - mx);
                s[j][2 * rh] = e0;
                s[j][2 * rh + 1] = e1;
                sum += e0 + e1;
            }
            sum += __shfl_xor_sync(0xffffffffu, sum, 1);
            sum += __shfl_xor_sync(0xffffffffu, sum, 2);
            inv[rh] = 1.f / sum;
        }

        // P -> A-frags in registers
        u32 ph[4][4], pl[4][4];
        #pragma unroll
        for (int kk = 0; kk < 4; ++kk) {
            bsplit(s[2 * kk][0] * inv[0], s[2 * kk][1] * inv[0], ph[kk][0], pl[kk][0]);
            bsplit(s[2 * kk][2] * inv[1], s[2 * kk][3] * inv[1], ph[kk][1], pl[kk][1]);
            bsplit(s[2 * kk + 1][0] * inv[0], s[2 * kk + 1][1] * inv[0], ph[kk][2], pl[kk][2]);
            bsplit(s[2 * kk + 1][2] * inv[1], s[2 * kk + 1][3] * inv[1], ph[kk][3], pl[kk][3]);
        }

        // PV
        float o[4][4];
        #pragma unroll
        for (int jd = 0; jd < 4; ++jd)
            #pragma unroll
            for (int q = 0; q < 4; ++q) o[jd][q] = 0.f;
        {
            const uint2* vfH = (const uint2*)(smem + SM_VF_H);
            const uint2* vfL = (const uint2*)(smem + SM_VF_L);
            #pragma unroll
            for (int kk = 0; kk < 4; ++kk) {
                #pragma unroll
                for (int jd = 0; jd < 4; ++jd) {
                    uint2 bh2 = vfH[(kk * 16 + 4 * h + jd) * 32 + lane];
                    uint2 bl2 = vfL[(kk * 16 + 4 * h + jd) * 32 + lane];
                    u32 bH[2] = {bh2.x, bh2.y};
                    u32 bL[2] = {bl2.x, bl2.y};
                    mma_bf16(o[jd], ph[kk], bH);
                    mma_bf16(o[jd], ph[kk], bL);
                    mma_bf16(o[jd], pl[kk], bH);
                }
            }
        }

        // ao -> A-frags (overlay Q region)
        {
            uint4* aoH = (uint4*)(smem + SM_QF_H);
            uint4* aoL = (uint4*)(smem + SM_QF_L);
            #pragma unroll
            for (int kd = 0; kd < 2; ++kd) {
                u32 h0, l0, h1, l1, h2, l2, h3, l3;
                bsplit(o[2 * kd][0], o[2 * kd][1], h0, l0);
                bsplit(o[2 * kd][2], o[2 * kd][3], h1, l1);
                bsplit(o[2 * kd + 1][0], o[2 * kd + 1][1], h2, l2);
                bsplit(o[2 * kd + 1][2], o[2 * kd + 1][3], h3, l3);
                const int off = ((2 * h + kd) * 4 + t) * 32 + lane;
                aoH[off] = make_uint4(h0, h1, h2, h3);
                aoL[off] = make_uint4(l0, l1, l2, l3);
            }
        }
    }
    cp_wait<0>();
    __syncthreads();

    // ---- P4: proj, 16 warps: warp = (m16 tile mw, 32-col group nw2) ----
    {
        const int mw  = warp & 3;
        const int nw2 = warp >> 2;
        const u32* aoH = (const u32*)(smem + SM_QF_H);
        const u32* aoL = (const u32*)(smem + SM_QF_L);
        const u32* pwH = (const u32*)(smem + SM_PWH);
        const u32* pwL = (const u32*)(smem + SM_PWL);

        float c[4][4];
        #pragma unroll
        for (int j = 0; j < 4; ++j)
            #pragma unroll
            for (int q = 0; q < 4; ++q) c[j][q] = 0.f;

        #pragma unroll
        for (int k16 = 0; k16 < 8; ++k16) {
            u32 aH[4], aL[4];
            uint4 vh = *(const uint4*)&aoH[((k16 * 4 + mw) * 32 + lane) * 4];
            uint4 vl = *(const uint4*)&aoL[((k16 * 4 + mw) * 32 + lane) * 4];
            aH[0] = vh.x; aH[1] = vh.y; aH[2] = vh.z; aH[3] = vh.w;
            aL[0] = vl.x; aL[1] = vl.y; aL[2] = vl.z; aL[3] = vl.w;
            #pragma unroll
            for (int j = 0; j < 4; ++j) {
                const int off = ((k16 * 16 + nw2 * 4 + j) * 32 + lane) * 2;
                u32 bH[2], bL[2];
                *(uint2*)bH = *(const uint2*)&pwH[off];
                *(uint2*)bL = *(const uint2*)&pwL[off];
                mma_bf16(c[j], aH, bH);
                mma_bf16(c[j], aH, bL);
                mma_bf16(c[j], aL, bH);
            }
        }

        float* ob = out + (size_t)b * (N_TOK * CDIM);
        const int r0 = mw * 16 + g;
        const int r1 = r0 + 8;
        #pragma unroll
        for (int j = 0; j < 4; ++j) {
            const int col = nw2 * 32 + j * 8 + 2 * tig;
            const float b0 = proj_b[col], b1 = proj_b[col + 1];
            if (r0 < N_TOK)
                *(float2*)&ob[r0 * CDIM + col] = make_float2(c[j][0] + b0, c[j][1] + b1);
            if (r1 < N_TOK)
                *(float2*)&ob[r1 * CDIM + col] = make_float2(c[j][2] + b0, c[j][3] + b1);
        }
    }
}

extern "C" void kernel_launch(void* const* d_in, const int* in_sizes, int n_in,
                              void* d_out, int out_size)
{
    const float* x          = (const float*)d_in[0];
    const float* mask       = (const float*)d_in[1];
    const float* qkv_w      = (const float*)d_in[2];
    const float* qkv_b      = (const float*)d_in[3];
    const float* proj_w     = (const float*)d_in[4];
    const float* proj_b     = (const float*)d_in[5];
    const float* bias_table = (const float*)d_in[6];
    const int*   rel_index  = (const int*)d_in[7];
    float* out = (float*)d_out;

    const int B = in_sizes[0] / (N_TOK * CDIM);

    {
        const int TOT = NWIN * NH * 4 * 8 * 32 * 4;
        build_abias_kernel<<<(TOT + 255) / 256, 256>>>(mask, bias_table, rel_index);
    }
    {
        u32 *dH, *dL;
        cudaGetSymbolAddress((void**)&dH, g_wqkvH);
        cudaGetSymbolAddress((void**)&dL, g_wqkvL);
        pack_w_kernel<<<(8 * 48 * 32 + 255) / 256, 256>>>(qkv_w, dH, dL, QKV_N, 48, 8 * 48 * 32);
        cudaGetSymbolAddress((void**)&dH, g_wprojH);
        cudaGetSymbolAddress((void**)&dL, g_wprojL);
        pack_w_kernel<<<(8 * 16 * 32 + 255) / 256, 256>>>(proj_w, dH, dL, CDIM, 16, 8 * 16 * 32);
    }

    cudaFuncSetAttribute(win_attn_kernel,
                         cudaFuncAttributeMaxDynamicSharedMemorySize, SMEM_BYTES);
    win_attn_kernel<<<B, NTHREADS, SMEM_BYTES>>>(x, qkv_b, proj_b, out);
}

// round 8
// speedup vs baseline: 2.8115x; 1.0722x over previous
#include <cuda_runtime.h>
#include <cuda_bf16.h>

#define N_TOK    49
#define CDIM     128
#define NH       4
#define DH       32
#define QKV_N    384
#define NWIN     64
#define NTHREADS 512
#define SCALE    0.17677669529663687f

// ---- smem layout (bytes) ----
#define SM_QF_H   0          // Q A-frags / later ao A-frags (overlay)
#define SM_QF_L   16384
#define SM_KF_H   32768
#define SM_KF_L   49152
#define SM_VF_H   65536
#define SM_VF_L   81920
#define SM_XFH    98304      // x A-frags
#define SM_XFL    114688
#define SM_PWH    131072     // proj weights hi
#define SM_PWL    163840     // proj weights lo
#define SMEM_BYTES 196608

typedef unsigned long long u64;
typedef unsigned int u32;

// ---------------- device globals ----------------
__device__ float g_abias_frag[NWIN * NH * 4 * 8 * 32 * 4];  // [w][h][t][j][lane][q]
__device__ u32 g_wqkvH[8 * 48 * 32 * 2];   // [k16][n8][lane][2]
__device__ u32 g_wqkvL[8 * 48 * 32 * 2];
__device__ u32 g_wprojH[8 * 16 * 32 * 2];
__device__ u32 g_wprojL[8 * 16 * 32 * 2];

// ---------------- helpers ----------------
__device__ __forceinline__ u64 pack2(float lo, float hi) {
    u64 r; asm("mov.b64 %0, {%1, %2};" : "=l"(r) : "f"(lo), "f"(hi)); return r;
}
__device__ __forceinline__ void unpack2(u64 v, float& lo, float& hi) {
    asm("mov.b64 {%0, %1}, %2;" : "=f"(lo), "=f"(hi) : "l"(v));
}
__device__ __forceinline__ void bsplit(float a, float b, u32& hi, u32& lo) {
    __nv_bfloat16 ah = __float2bfloat16(a), bh = __float2bfloat16(b);
    __nv_bfloat16 al = __float2bfloat16(a - __bfloat162float(ah));
    __nv_bfloat16 bl = __float2bfloat16(b - __bfloat162float(bh));
    hi = (u32)__bfloat16_as_ushort(ah) | ((u32)__bfloat16_as_ushort(bh) << 16);
    lo = (u32)__bfloat16_as_ushort(al) | ((u32)__bfloat16_as_ushort(bl) << 16);
}
__device__ __forceinline__ void mma_bf16(float c[4], const u32 a[4], const u32 b[2]) {
    asm volatile("mma.sync.aligned.m16n8k16.row.col.f32.bf16.bf16.f32 "
                 "{%0,%1,%2,%3}, {%4,%5,%6,%7}, {%8,%9}, {%0,%1,%2,%3};"
                 : "+f"(c[0]), "+f"(c[1]), "+f"(c[2]), "+f"(c[3])
                 : "r"(a[0]), "r"(a[1]), "r"(a[2]), "r"(a[3]), "r"(b[0]), "r"(b[1]));
}
__device__ __forceinline__ void cp16(u32 daddr, const void* src) {
    asm volatile("cp.async.cg.shared.global [%0], [%1], 16;" :: "r"(daddr), "l"(src));
}
__device__ __forceinline__ void cp_commit() { asm volatile("cp.async.commit_group;"); }
template <int N> __device__ __forceinline__ void cp_wait() {
    asm volatile("cp.async.wait_group %0;" :: "n"(N));
}

// ---------------- prep kernels ----------------
__global__ void build_abias_kernel(const float* __restrict__ mask,
                                   const float* __restrict__ bias_table,
                                   const int*   __restrict__ rel_index)
{
    int idx = blockIdx.x * blockDim.x + threadIdx.x;
    const int TOT = NWIN * NH * 4 * 8 * 32 * 4;
    if (idx >= TOT) return;
    int q    = idx & 3;
    int lane = (idx >> 2) & 31;
    int j    = (idx >> 7) & 7;
    int t    = (idx >> 10) & 3;
    int h    = (idx >> 12) & 3;
    int w    = idx >> 14;
    int g = lane >> 2, tig = lane & 3;
    int i = 16 * t + g + 8 * (q >> 1);
    int m = j * 8 + 2 * tig + (q & 1);
    float v;
    if (m >= N_TOK)      v = -1e9f;
    else if (i >= N_TOK) v = 0.f;
    else v = bias_table[rel_index[i * N_TOK + m] * NH + h]
           + mask[(w * N_TOK + i) * N_TOK + m];
    g_abias_frag[idx] = v;
}

__global__ void pack_w_kernel(const float* __restrict__ W, u32* dH, u32* dL,
                              int N, int nn8, int total)
{
    int s = blockIdx.x * blockDim.x + threadIdx.x;
    if (s >= total) return;
    int ln  = s & 31;
    int n8  = (s >> 5) % nn8;
    int k16 = s / (nn8 * 32);
    int gg = ln >> 2, tt = ln & 3;
    int col = n8 * 8 + gg;
    int r = k16 * 16 + 2 * tt;
    float w0 = W[(r + 0) * N + col], w1 = W[(r + 1) * N + col];
    float w2 = W[(r + 8) * N + col], w3 = W[(r + 9) * N + col];
    u32 h0, l0, h1, l1;
    bsplit(w0, w1, h0, l0);
    bsplit(w2, w3, h1, l1);
    dH[s * 2] = h0; dH[s * 2 + 1] = h1;
    dL[s * 2] = l0; dL[s * 2 + 1] = l1;
}

// ---------------- main kernel ----------------
__global__ void __launch_bounds__(NTHREADS, 1)
win_attn_kernel(const float* __restrict__ x,
                const float* __restrict__ qkv_b,
                const float* __restrict__ proj_b,
                float* __restrict__ out)
{
    extern __shared__ char smem[];
    const u32 smem_u32 = (u32)__cvta_generic_to_shared(smem);

    const int b    = blockIdx.x;
    const int tid  = threadIdx.x;
    const int warp = tid >> 5;
    const int lane = tid & 31;
    const int g    = lane >> 2;
    const int tig  = lane & 3;

    const int mw = warp & 1;          // P2: rows mw*32..+31
    const int nw = warp >> 1;         // P2: cols nw*48..+47

    // ---- prefetch first weight half-tile (k16=0, j=0..2) into registers ----
    u32 bh[2][3][2], bl[2][3][2];
    #pragma unroll
    for (int jj = 0; jj < 3; ++jj) {
        const int off = ((nw * 6 + jj) * 32 + lane) * 2;
        *(uint2*)bh[0][jj] = *(const uint2*)&g_wqkvH[off];
        *(uint2*)bl[0][jj] = *(const uint2*)&g_wqkvL[off];
    }

    // ---- P0: pack x into A-fragments (bf16 hi/lo), rows >=49 zero ----
    {
        const float* xb = x + (size_t)b * (N_TOK * CDIM);
        u32* xfH = (u32*)(smem + SM_XFH);
        u32* xfL = (u32*)(smem + SM_XFL);
        #pragma unroll
        for (int it = 0; it < 2; ++it) {
            int s = tid + it * NTHREADS;
            int k16 = s >> 7, m16 = (s >> 5) & 3, ln = s & 31;
            int gg = ln >> 2, tt = ln & 3;
            int r0 = m16 * 16 + gg, r1 = r0 + 8;
            int c0 = k16 * 16 + 2 * tt;
            float2 p00 = (r0 < N_TOK) ? *(const float2*)&xb[r0 * CDIM + c0]     : make_float2(0.f, 0.f);
            float2 p10 = (r1 < N_TOK) ? *(const float2*)&xb[r1 * CDIM + c0]     : make_float2(0.f, 0.f);
            float2 p01 = (r0 < N_TOK) ? *(const float2*)&xb[r0 * CDIM + c0 + 8] : make_float2(0.f, 0.f);
            float2 p11 = (r1 < N_TOK) ? *(const float2*)&xb[r1 * CDIM + c0 + 8] : make_float2(0.f, 0.f);
            u32 h[4], l[4];
            bsplit(p00.x, p00.y, h[0], l[0]);
            bsplit(p10.x, p10.y, h[1], l[1]);
            bsplit(p01.x, p01.y, h[2], l[2]);
            bsplit(p11.x, p11.y, h[3], l[3]);
            *(uint4*)&xfH[s * 4] = make_uint4(h[0], h[1], h[2], h[3]);
            *(uint4*)&xfL[s * 4] = make_uint4(l[0], l[1], l[2], l[3]);
        }
    }
    __syncthreads();

    // ---- P2: qkv GEMM, 16 warps, 32x48 tiles, weights L2->regs, NO barriers ----
    {
        const u32* xfH = (const u32*)(smem + SM_XFH);
        const u32* xfL = (const u32*)(smem + SM_XFL);

        float c[2][6][4];
        #pragma unroll
        for (int tp = 0; tp < 2; ++tp)
            #pragma unroll
            for (int j = 0; j < 6; ++j)
                #pragma unroll
                for (int q = 0; q < 4; ++q) c[tp][j][q] = 0.f;

        u32 aH[2][4], aL[2][4];

        #pragma unroll
        for (int s = 0; s < 16; ++s) {
            const int k16 = s >> 1;
            const int jh  = s & 1;           // half: j = jh*3 .. jh*3+2
            const int cur = s & 1;
            const int nxt = cur ^ 1;

            if (s < 15) {                    // prefetch next half-tile
                const int s2 = s + 1;
                const int k16n = s2 >> 1, jhn = s2 & 1;
                #pragma unroll
                for (int jj = 0; jj < 3; ++jj) {
                    const int off = ((k16n * 48 + nw * 6 + jhn * 3 + jj) * 32 + lane) * 2;
                    *(uint2*)bh[nxt][jj] = *(const uint2*)&g_wqkvH[off];
                    *(uint2*)bl[nxt][jj] = *(const uint2*)&g_wqkvL[off];
                }
            }
            if (jh == 0) {                   // A-frags once per k16
                #pragma unroll
                for (int tp = 0; tp < 2; ++tp) {
                    const int t = 2 * mw + tp;
                    uint4 vh = *(const uint4*)&xfH[((k16 * 4 + t) * 32 + lane) * 4];
                    uint4 vl = *(const uint4*)&xfL[((k16 * 4 + t) * 32 + lane) * 4];
                    aH[tp][0] = vh.x; aH[tp][1] = vh.y; aH[tp][2] = vh.z; aH[tp][3] = vh.w;
                    aL[tp][0] = vl.x; aL[tp][1] = vl.y; aL[tp][2] = vl.z; aL[tp][3] = vl.w;
                }
            }
            #pragma unroll
            for (int tp = 0; tp < 2; ++tp) {
                #pragma unroll
                for (int jj = 0; jj < 3; ++jj) {
                    const int j = jh * 3 + jj;
                    mma_bf16(c[tp][j], aH[tp], bh[cur][jj]);
                    mma_bf16(c[tp][j], aH[tp], bl[cur][jj]);
                    mma_bf16(c[tp][j], aL[tp], bh[cur][jj]);
                }
            }
        }

        // ---- epilogue: per-k16 region dispatch (Q A-frag / K B-frag / V B-frag) ----
        float bias0[6], bias1[6];
        #pragma unroll
        for (int j = 0; j < 6; ++j) {
            const int gcol = nw * 48 + j * 8 + 2 * tig;
            bias0[j] = qkv_b[gcol];
            bias1[j] = qkv_b[gcol + 1];
        }

        #pragma unroll
        for (int lk = 0; lk < 3; ++lk) {
            const int gk16 = nw * 3 + lk;     // global col-k16, 0..23
            const int j0 = 2 * lk, j1 = 2 * lk + 1;
            if (gk16 < 8) {
                // ---- Q: A-frag layout, +bias, *SCALE ----
                uint4* qfH = (uint4*)(smem + SM_QF_H);
                uint4* qfL = (uint4*)(smem + SM_QF_L);
                #pragma unroll
                for (int tp = 0; tp < 2; ++tp) {
                    const int t = 2 * mw + tp;
                    float v0 = (c[tp][j0][0] + bias0[j0]) * SCALE;
                    float v1 = (c[tp][j0][1] + bias1[j0]) * SCALE;
                    float v2 = (c[tp][j0][2] + bias0[j0]) * SCALE;
                    float v3 = (c[tp][j0][3] + bias1[j0]) * SCALE;
                    float v4 = (c[tp][j1][0] + bias0[j1]) * SCALE;
                    float v5 = (c[tp][j1][1] + bias1[j1]) * SCALE;
                    float v6 = (c[tp][j1][2] + bias0[j1]) * SCALE;
                    float v7 = (c[tp][j1][3] + bias1[j1]) * SCALE;
                    u32 h0, l0, h1, l1, h2, l2, h3, l3;
                    bsplit(v0, v1, h0, l0);
                    bsplit(v2, v3, h1, l1);
                    bsplit(v4, v5, h2, l2);
                    bsplit(v6, v7, h3, l3);
                    const int off = (gk16 * 4 + t) * 32 + lane;
                    qfH[off] = make_uint4(h0, h1, h2, h3);
                    qfL[off] = make_uint4(l0, l1, l2, l3);
                }
            } else if (gk16 < 16) {
                // ---- K: B-frag layout (same-lane repack) ----
                const int kk16 = gk16 - 8;
                uint2* kfH = (uint2*)(smem + SM_KF_H);
                uint2* kfL = (uint2*)(smem + SM_KF_L);
                #pragma unroll
                for (int tp = 0; tp < 2; ++tp) {
                    const int t = 2 * mw + tp;
                    u32 h00, l00, h01, l01, h10, l10, h11, l11;
                    bsplit(c[tp][j0][0] + bias0[j0], c[tp][j0][1] + bias1[j0], h00, l00);
                    bsplit(c[tp][j1][0] + bias0[j1], c[tp][j1][1] + bias1[j1], h01, l01);
                    bsplit(c[tp][j0][2] + bias0[j0], c[tp][j0][3] + bias1[j0], h10, l10);
                    bsplit(c[tp][j1][2] + bias0[j1], c[tp][j1][3] + bias1[j1], h11, l11);
                    kfH[(kk16 * 8 + 2 * t) * 32 + lane]     = make_uint2(h00, h01);
                    kfH[(kk16 * 8 + 2 * t + 1) * 32 + lane] = make_uint2(h10, h11);
                    kfL[(kk16 * 8 + 2 * t) * 32 + lane]     = make_uint2(l00, l01);
                    kfL[(kk16 * 8 + 2 * t + 1) * 32 + lane] = make_uint2(l10, l11);
                }
            } else {
                // ---- V: B-frag layout (key-pair transpose via xor-4 shuffle) ----
                uint2* vfH = (uint2*)(smem + SM_VF_H);
                uint2* vfL = (uint2*)(smem + SM_VF_L);
                #pragma unroll
                for (int jj = 0; jj < 2; ++jj) {
                    const int j = 2 * lk + jj;
                    const int n8v = (gk16 - 16) * 2 + jj;  // 0..15
                    #pragma unroll
                    for (int tp = 0; tp < 2; ++tp) {
                        const int t = 2 * mw + tp;
                        float c0 = c[tp][j][0] + bias0[j];
                        float c1 = c[tp][j][1] + bias1[j];
                        float c2 = c[tp][j][2] + bias0[j];
                        float c3 = c[tp][j][3] + bias1[j];
                        u64 p01 = pack2(c0, c1), p23 = pack2(c2, c3);
                        u64 r01 = __shfl_xor_sync(0xffffffffu, p01, 4);
                        u64 r23 = __shfl_xor_sync(0xffffffffu, p23, 4);
                        if (!(g & 1)) {
                            float e0, e1, e2, e3;
                            unpack2(r01, e0, e1);
                            unpack2(r23, e2, e3);
                            u32 h00, l00, h01, l01, h10, l10, h11, l11;
                            bsplit(c0, e0, h00, l00);
                            bsplit(c2, e2, h01, l01);
                            bsplit(c1, e1, h10, l10);
                            bsplit(c3, e3, h11, l11);
                            const int kp2 = g >> 1;
                            const int base = (t * 16 + n8v) * 32;
                            vfH[base + (2 * tig) * 4 + kp2]     = make_uint2(h00, h01);
                            vfH[base + (2 * tig + 1) * 4 + kp2] = make_uint2(h10, h11);
                            vfL[base + (2 * tig) * 4 + kp2]     = make_uint2(l00, l01);
                            vfL[base + (2 * tig + 1) * 4 + kp2] = make_uint2(l10, l11);
                        }
                    }
                }
            }
        }
    }

    // ---- stage proj weights via cp.async (lands during attention) ----
    {
        const uint4* srcH = (const uint4*)g_wprojH;
        const uint4* srcL = (const uint4*)g_wprojL;
        const u32 dH = smem_u32 + SM_PWH;
        const u32 dL = smem_u32 + SM_PWL;
        #pragma unroll
        for (int i = 0; i < 4; ++i) {
            const int idx = tid + i * NTHREADS;
            cp16(dH + idx * 16, srcH + idx);
            cp16(dL + idx * 16, srcL + idx);
        }
        cp_commit();
    }
    __syncthreads();

    // ---- P3: attention on tensor cores, 16 warps: warp = (head h, m16 tile t) ----
    {
        const int h = warp >> 2;
        const int t = warp & 3;

        // Q A-frags
        u32 qh[2][4], ql[2][4];
        {
            const uint4* qfH = (const uint4*)(smem + SM_QF_H);
            const uint4* qfL = (const uint4*)(smem + SM_QF_L);
            #pragma unroll
            for (int kk = 0; kk < 2; ++kk) {
                const int off = ((2 * h + kk) * 4 + t) * 32 + lane;
                uint4 vh = qfH[off], vl = qfL[off];
                qh[kk][0] = vh.x; qh[kk][1] = vh.y; qh[kk][2] = vh.z; qh[kk][3] = vh.w;
                ql[kk][0] = vl.x; ql[kk][1] = vl.y; ql[kk][2] = vl.z; ql[kk][3] = vl.w;
            }
        }

        // scores
        float s[8][4];
        #pragma unroll
        for (int j = 0; j < 8; ++j)
            #pragma unroll
            for (int q = 0; q < 4; ++q) s[j][q] = 0.f;
        {
            const uint2* kfH = (const uint2*)(smem + SM_KF_H);
            const uint2* kfL = (const uint2*)(smem + SM_KF_L);
            #pragma unroll
            for (int kk = 0; kk < 2; ++kk) {
                #pragma unroll
                for (int j = 0; j < 8; ++j) {
                    uint2 bh2 = kfH[((2 * h + kk) * 8 + j) * 32 + lane];
                    uint2 bl2 = kfL[((2 * h + kk) * 8 + j) * 32 + lane];
                    u32 bH[2] = {bh2.x, bh2.y};
                    u32 bL[2] = {bl2.x, bl2.y};
                    mma_bf16(s[j], qh[kk], bH);
                    mma_bf16(s[j], qh[kk], bL);
                    mma_bf16(s[j], ql[kk], bH);
                }
            }
        }

        // bias + mask (fragment-ordered)
        {
            const int w = b & (NWIN - 1);
            const float4* ab = (const float4*)(g_abias_frag + (size_t)(w * NH + h) * 4096);
            #pragma unroll
            for (int j = 0; j < 8; ++j) {
                float4 bb = ab[(t * 8 + j) * 32 + lane];
                s[j][0] += bb.x; s[j][1] += bb.y;
                s[j][2] += bb.z; s[j][3] += bb.w;
            }
        }

        // softmax
        float inv[2];
        #pragma unroll
        for (int rh = 0; rh < 2; ++rh) {
            float mx = -1e30f;
            #pragma unroll
            for (int j = 0; j < 8; ++j) {
                mx = fmaxf(mx, s[j][2 * rh]);
                mx = fmaxf(mx, s[j][2 * rh + 1]);
            }
            mx = fmaxf(mx, __shfl_xor_sync(0xffffffffu, mx, 1));
            mx = fmaxf(mx, __shfl_xor_sync(0xffffffffu, mx, 2));
            float sum = 0.f;
            #pragma unroll
            for (int j = 0; j < 8; ++j) {
                float e0 = __expf(s[j][2 * rh] - mx);
                float e1 = __expf(s[j][2 * rh + 1] - mx);
                s[j][2 * rh] = e0;
                s[j][2 * rh + 1] = e1;
                sum += e0 + e1;
            }
            sum += __shfl_xor_sync(0xffffffffu, sum, 1);
            sum += __shfl_xor_sync(0xffffffffu, sum, 2);
            inv[rh] = 1.f / sum;
        }

        // P -> A-frags in registers
        u32 ph[4][4], pl[4][4];
        #pragma unroll
        for (int kk = 0; kk < 4; ++kk) {
            bsplit(s[2 * kk][0] * inv[0], s[2 * kk][1] * inv[0], ph[kk][0], pl[kk][0]);
            bsplit(s[2 * kk][2] * inv[1], s[2 * kk][3] * inv[1], ph[kk][1], pl[kk][1]);
            bsplit(s[2 * kk + 1][0] * inv[0], s[2 * kk + 1][1] * inv[0], ph[kk][2], pl[kk][2]);
            bsplit(s[2 * kk + 1][2] * inv[1], s[2 * kk + 1][3] * inv[1], ph[kk][3], pl[kk][3]);
        }

        // PV
        float o[4][4];
        #pragma unroll
        for (int jd = 0; jd < 4; ++jd)
            #pragma unroll
            for (int q = 0; q < 4; ++q) o[jd][q] = 0.f;
        {
            const uint2* vfH = (const uint2*)(smem + SM_VF_H);
            const uint2* vfL = (const uint2*)(smem + SM_VF_L);
            #pragma unroll
            for (int kk = 0; kk < 4; ++kk) {
                #pragma unroll
                for (int jd = 0; jd < 4; ++jd) {
                    uint2 bh2 = vfH[(kk * 16 + 4 * h + jd) * 32 + lane];
                    uint2 bl2 = vfL[(kk * 16 + 4 * h + jd) * 32 + lane];
                    u32 bH[2] = {bh2.x, bh2.y};
                    u32 bL[2] = {bl2.x, bl2.y};
                    mma_bf16(o[jd], ph[kk], bH);
                    mma_bf16(o[jd], ph[kk], bL);
                    mma_bf16(o[jd], pl[kk], bH);
                }
            }
        }

        // ao -> A-frags (overlay Q region)
        {
            uint4* aoH = (uint4*)(smem + SM_QF_H);
            uint4* aoL = (uint4*)(smem + SM_QF_L);
            #pragma unroll
            for (int kd = 0; kd < 2; ++kd) {
                u32 h0, l0, h1, l1, h2, l2, h3, l3;
                bsplit(o[2 * kd][0], o[2 * kd][1], h0, l0);
                bsplit(o[2 * kd][2], o[2 * kd][3], h1, l1);
                bsplit(o[2 * kd + 1][0], o[2 * kd + 1][1], h2, l2);
                bsplit(o[2 * kd + 1][2], o[2 * kd + 1][3], h3, l3);
                const int off = ((2 * h + kd) * 4 + t) * 32 + lane;
                aoH[off] = make_uint4(h0, h1, h2, h3);
                aoL[off] = make_uint4(l0, l1, l2, l3);
            }
        }
    }
    cp_wait<0>();
    __syncthreads();

    // ---- P4: proj, 16 warps: warp = (m16 tile mw2, 32-col group nw2) ----
    {
        const int mw2 = warp & 3;
        const int nw2 = warp >> 2;
        const u32* aoH = (const u32*)(smem + SM_QF_H);
        const u32* aoL = (const u32*)(smem + SM_QF_L);
        const u32* pwH = (const u32*)(smem + SM_PWH);
        const u32* pwL = (const u32*)(smem + SM_PWL);

        float c[4][4];
        #pragma unroll
        for (int j = 0; j < 4; ++j)
            #pragma unroll
            for (int q = 0; q < 4; ++q) c[j][q] = 0.f;

        #pragma unroll
        for (int k16 = 0; k16 < 8; ++k16) {
            u32 aH[4], aL[4];
            uint4 vh = *(const uint4*)&aoH[((k16 * 4 + mw2) * 32 + lane) * 4];
            uint4 vl = *(const uint4*)&aoL[((k16 * 4 + mw2) * 32 + lane) * 4];
            aH[0] = vh.x; aH[1] = vh.y; aH[2] = vh.z; aH[3] = vh.w;
            aL[0] = vl.x; aL[1] = vl.y; aL[2] = vl.z; aL[3] = vl.w;
            #pragma unroll
            for (int j = 0; j < 4; ++j) {
                const int off = ((k16 * 16 + nw2 * 4 + j) * 32 + lane) * 2;
                u32 bH[2], bL[2];
                *(uint2*)bH = *(const uint2*)&pwH[off];
                *(uint2*)bL = *(const uint2*)&pwL[off];
                mma_bf16(c[j], aH, bH);
                mma_bf16(c[j], aH, bL);
                mma_bf16(c[j], aL, bH);
            }
        }

        float* ob = out + (size_t)b * (N_TOK * CDIM);
        const int r0 = mw2 * 16 + g;
        const int r1 = r0 + 8;
        #pragma unroll
        for (int j = 0; j < 4; ++j) {
            const int col = nw2 * 32 + j * 8 + 2 * tig;
            const float b0 = proj_b[col], b1 = proj_b[col + 1];
            if (r0 < N_TOK)
                *(float2*)&ob[r0 * CDIM + col] = make_float2(c[j][0] + b0, c[j][1] + b1);
            if (r1 < N_TOK)
                *(float2*)&ob[r1 * CDIM + col] = make_float2(c[j][2] + b0, c[j][3] + b1);
        }
    }
}

extern "C" void kernel_launch(void* const* d_in, const int* in_sizes, int n_in,
                              void* d_out, int out_size)
{
    const float* x          = (const float*)d_in[0];
    const float* mask       = (const float*)d_in[1];
    const float* qkv_w      = (const float*)d_in[2];
    const float* qkv_b      = (const float*)d_in[3];
    const float* proj_w     = (const float*)d_in[4];
    const float* proj_b     = (const float*)d_in[5];
    const float* bias_table = (const float*)d_in[6];
    const int*   rel_index  = (const int*)d_in[7];
    float* out = (float*)d_out;

    const int B = in_sizes[0] / (N_TOK * CDIM);

    {
        const int TOT = NWIN * NH * 4 * 8 * 32 * 4;
        build_abias_kernel<<<(TOT + 255) / 256, 256>>>(mask, bias_table, rel_index);
    }
    {
        u32 *dH, *dL;
        cudaGetSymbolAddress((void**)&dH, g_wqkvH);
        cudaGetSymbolAddress((void**)&dL, g_wqkvL);
        pack_w_kernel<<<(8 * 48 * 32 + 255) / 256, 256>>>(qkv_w, dH, dL, QKV_N, 48, 8 * 48 * 32);
        cudaGetSymbolAddress((void**)&dH, g_wprojH);
        cudaGetSymbolAddress((void**)&dL, g_wprojL);
        pack_w_kernel<<<(8 * 16 * 32 + 255) / 256, 256>>>(proj_w, dH, dL, CDIM, 16, 8 * 16 * 32);
    }

    cudaFuncSetAttribute(win_attn_kernel,
                         cudaFuncAttributeMaxDynamicSharedMemorySize, SMEM_BYTES);
    win_attn_kernel<<<B, NTHREADS, SMEM_BYTES>>>(x, qkv_b, proj_b, out);
}